// round 4
// baseline (speedup 1.0000x reference)
#include <cuda_runtime.h>
#include <cstdint>

// Problem dims
#define NB    128
#define NT    96
#define ND    256
#define NH    256
#define NC    8
#define NM    64
#define NCM   512           // NC*NM
#define NCOMB 1280          // 4*ND + NH
#define GRID  128           // persistent CTAs (<= 148 SMs -> all co-resident)
#define NTHR  256
#define SMEM_FLOATS (NCOMB * 17)          // stride-17 padded [k][bi] tile, bi=0..15
#define SMEM_BYTES  (SMEM_FLOATS * 4)     // 87040 B

// ---------------- device scratch (static, no allocation) ----------------
__device__ float g_Z [NB*NT*ND];
__device__ float g_ZP[NB*NT*ND];
__device__ float g_LP[NB*NT*ND];   // lw0*z + lw1*zp
__device__ float g_h [NB*NH];
__device__ float g_c [NB*NH];
__device__ float g_xi[NB*ND];
__device__ float g_gd[NB*ND];
__device__ float g_sc[NB*NCM];
__device__ float g_mm[NCM*ND];     // cluster-masked memory
__device__ unsigned int g_arrive;
__device__ unsigned int g_release;

// ---------------- prep: h-independent precompute ----------------
__global__ void prep_kernel(const float* __restrict__ x,
                            const float* __restrict__ xmean,
                            const int*   __restrict__ cl32,   // clusters (int32 or int64 payload)
                            const float* __restrict__ gz_w,  const float* __restrict__ gz_b,
                            const float* __restrict__ gzp_w, const float* __restrict__ gzp_b,
                            const float* __restrict__ memory,
                            const float* __restrict__ local_w)
{
    int tid  = blockIdx.x * blockDim.x + threadIdx.x;
    int nthr = gridDim.x * blockDim.x;
    // detect int64 clusters: values are 1..8 so the high 32-bit word of elem0 is 0
    bool is64 = (cl32[1] == 0);

    for (int i = tid; i < NB*NT*ND; i += nthr) {
        int d = i & (ND - 1);
        int t = (i / ND) % NT;
        int b = i / (ND * NT);
        long long o = (((long long)b * 6) * NT + t) * ND + d;   // x[b, s, t, d], s stride = NT*ND
        float xt  = x[o];
        float xl  = x[o + 1ll*NT*ND];
        float mk  = x[o + 2ll*NT*ND];
        float dt  = x[o + 3ll*NT*ND];
        float xlb = x[o + 4ll*NT*ND];
        float dtb = x[o + 5ll*NT*ND];
        float mean = xmean[t*ND + d];
        float a   = fmaxf(dt  * gz_w[d]  + gz_b[d],  0.f);
        float dz  = expf(-a);
        float ab  = fmaxf(dtb * gzp_w[d] + gzp_b[d], 0.f);
        float dzp = expf(-ab);
        float z  = mk*xt + (1.f - mk)*(dz *xl  + (1.f - dz )*mean);
        float zp = mk*xt + (1.f - mk)*(dzp*xlb + (1.f - dzp)*mean);
        g_Z[i]  = z;
        g_ZP[i] = zp;
        g_LP[i] = local_w[d]*z + local_w[ND + d]*zp;
    }
    for (int i = tid; i < NCM*ND; i += nthr) {
        int d = i & (ND - 1);
        int c = i / (NM * ND);
        int cv = is64 ? cl32[2*d] : cl32[d];
        g_mm[i] = (cv == c + 1) ? memory[i] : 0.f;
    }
    for (int i = tid; i < NB*NH; i += nthr) { g_h[i] = 0.f; g_c[i] = 0.f; }
    if (blockIdx.x == 0 && threadIdx.x == 0) { g_arrive = 0u; g_release = 0u; }
}

// ---------------- grid barrier (monotonic, replay-safe: prep resets) ----------------
__device__ __forceinline__ void grid_sync(unsigned int& gen)
{
    __syncthreads();
    if (threadIdx.x == 0) {
        __threadfence();
        unsigned int target = gen + 1u;
        unsigned int a = atomicAdd(&g_arrive, 1u) + 1u;
        if (a == target * GRID) {
            atomicExch(&g_release, target);
        } else {
            volatile unsigned int* rel = &g_release;
            while (*rel < target) { __nanosleep(128); }
        }
        __threadfence();
    }
    gen += 1u;
    __syncthreads();
}

// ---------------- main persistent recurrence kernel ----------------
// CTA map: cta = bg*16 + sub ; bg in [0,8) -> 16 batch rows, sub in [0,16) -> phase-specific column slice.
__global__ void __launch_bounds__(NTHR, 1)
rnn_kernel(const float* __restrict__ W_i, const float* __restrict__ b_i,
           const float* __restrict__ W_f, const float* __restrict__ b_f,
           const float* __restrict__ W_o, const float* __restrict__ b_o,
           const float* __restrict__ W_c, const float* __restrict__ b_c,
           const float* __restrict__ W_fc, const float* __restrict__ b_fc,
           const float* __restrict__ memory,
           const float* __restrict__ global_w,
           const float* __restrict__ local_w,
           float* __restrict__ out)
{
    extern __shared__ float smem[];
    const int cta = blockIdx.x;
    const int bg  = cta >> 4;       // 0..7
    const int sub = cta & 15;       // 0..15
    const int tid = threadIdx.x;
    unsigned int gen = 0;

    for (int t = 0; t <= NT; ++t) {
        // ================= P1: x_i = h @ W_fc^T + b_fc ; out[:, t-1, :] = x_i =================
        {
            // stage h[bg tile][0..255] transposed (stride 17)
            for (int idx = tid; idx < 16 * NH; idx += NTHR) {
                int bi = idx / NH, k = idx % NH;
                smem[k*17 + bi] = __ldcg(&g_h[(bg*16 + bi)*NH + k]);
            }
            __syncthreads();
            const int bi = tid & 15, dl = tid >> 4;
            const int d = sub*16 + dl, b = bg*16 + bi;
            const float4* w4 = reinterpret_cast<const float4*>(W_fc + d*NH);
            const float* sp = smem + bi;
            float a0 = 0.f, a1 = 0.f;
            #pragma unroll 4
            for (int k4 = 0; k4 < NH/4; ++k4) {
                float4 w = w4[k4];
                int k = k4 * 4;
                a0 = fmaf(w.x, sp[(k+0)*17], fmaf(w.y, sp[(k+1)*17], a0));
                a1 = fmaf(w.z, sp[(k+2)*17], fmaf(w.w, sp[(k+3)*17], a1));
            }
            float acc = a0 + a1 + b_fc[d];
            g_xi[b*ND + d] = acc;
            if (t > 0) out[((size_t)b*NT + (t-1))*ND + d] = acc;
        }
        if (t == NT) break;
        grid_sync(gen);

        // ================= P2: scores[b][cm] = (LP + lw2*x_i) . memMasked[cm] =================
        {
            for (int idx = tid; idx < 16 * ND; idx += NTHR) {
                int bi = idx / ND, k = idx % ND;
                int b = bg*16 + bi;
                smem[k*17 + bi] = g_LP[(b*NT + t)*ND + k]
                                + local_w[2*ND + k] * __ldcg(&g_xi[b*ND + k]);
            }
            __syncthreads();
            const int bi = tid & 15, cl = tid >> 4;
            const int b = bg*16 + bi;
            const int cm0 = sub*32 + cl*2, cm1 = cm0 + 1;
            const float4* w0 = reinterpret_cast<const float4*>(g_mm + cm0*ND);
            const float4* w1 = reinterpret_cast<const float4*>(g_mm + cm1*ND);
            const float* sp = smem + bi;
            float s0 = 0.f, s1 = 0.f;
            #pragma unroll 4
            for (int k4 = 0; k4 < ND/4; ++k4) {
                float4 u = w0[k4], v = w1[k4];
                int k = k4 * 4;
                float e0 = sp[(k+0)*17], e1 = sp[(k+1)*17], e2 = sp[(k+2)*17], e3 = sp[(k+3)*17];
                s0 = fmaf(u.x,e0, fmaf(u.y,e1, fmaf(u.z,e2, fmaf(u.w,e3, s0))));
                s1 = fmaf(v.x,e0, fmaf(v.y,e1, fmaf(v.z,e2, fmaf(v.w,e3, s1))));
            }
            g_sc[b*NCM + cm0] = s0;
            g_sc[b*NCM + cm1] = s1;
        }
        grid_sync(gen);

        // ================= P3: s' = global_w[c]*softmax(scores) ; gd = s' @ memory =================
        {
            if (tid < 128) {   // (bi, ci): 16 x 8 softmax rows of length 64
                const int bi = tid & 15, ci = tid >> 4;
                const int b = bg*16 + bi;
                const float* sc = g_sc + b*NCM + ci*NM;
                float mx = -3.4e38f;
                #pragma unroll 4
                for (int m = 0; m < NM; ++m) mx = fmaxf(mx, __ldcg(&sc[m]));
                float sum = 0.f;
                #pragma unroll 4
                for (int m = 0; m < NM; ++m) sum += expf(__ldcg(&sc[m]) - mx);
                float inv = global_w[ci] / sum;
                #pragma unroll 4
                for (int m = 0; m < NM; ++m)
                    smem[(ci*NM + m)*17 + bi] = expf(__ldcg(&sc[m]) - mx) * inv;
            }
            __syncthreads();
            const int dl = tid & 15, bi = tid >> 4;   // lanes vary d -> coalesced memory reads
            const int d = sub*16 + dl, b = bg*16 + bi;
            const float* sp = smem + bi;
            float a0 = 0.f, a1 = 0.f;
            #pragma unroll 4
            for (int cm = 0; cm < NCM; cm += 2) {
                a0 = fmaf(sp[(cm+0)*17], memory[(cm+0)*ND + d], a0);
                a1 = fmaf(sp[(cm+1)*17], memory[(cm+1)*ND + d], a1);
            }
            g_gd[b*ND + d] = a0 + a1;
        }
        grid_sync(gen);

        // ================= P4: 4-gate GEMM over combined=[z,zp,x_i,gd,h] + state update =================
        {
            for (int idx = tid; idx < 16 * NCOMB; idx += NTHR) {
                int bi = idx / NCOMB, k = idx % NCOMB;
                int b = bg*16 + bi;
                float v;
                if      (k < 256)  v = g_Z [(b*NT + t)*ND + k];
                else if (k < 512)  v = g_ZP[(b*NT + t)*ND + (k - 256)];
                else if (k < 768)  v = __ldcg(&g_xi[b*ND + (k - 512)]);
                else if (k < 1024) v = __ldcg(&g_gd[b*ND + (k - 768)]);
                else               v = __ldcg(&g_h [b*NH + (k - 1024)]);
                smem[k*17 + bi] = v;
            }
            __syncthreads();
            const int bi = tid & 15, hl = tid >> 4;
            const int b = bg*16 + bi, hh = sub*16 + hl;
            const float4* wi = reinterpret_cast<const float4*>(W_i + hh*NCOMB);
            const float4* wf = reinterpret_cast<const float4*>(W_f + hh*NCOMB);
            const float4* wo = reinterpret_cast<const float4*>(W_o + hh*NCOMB);
            const float4* wc = reinterpret_cast<const float4*>(W_c + hh*NCOMB);
            const float* sp = smem + bi;
            float ai = 0.f, af = 0.f, ao = 0.f, ac = 0.f;
            #pragma unroll 2
            for (int k4 = 0; k4 < NCOMB/4; ++k4) {
                float4 vi = wi[k4], vf = wf[k4], vo = wo[k4], vc = wc[k4];
                int k = k4 * 4;
                float e0 = sp[(k+0)*17], e1 = sp[(k+1)*17], e2 = sp[(k+2)*17], e3 = sp[(k+3)*17];
                ai = fmaf(vi.x,e0, fmaf(vi.y,e1, fmaf(vi.z,e2, fmaf(vi.w,e3, ai))));
                af = fmaf(vf.x,e0, fmaf(vf.y,e1, fmaf(vf.z,e2, fmaf(vf.w,e3, af))));
                ao = fmaf(vo.x,e0, fmaf(vo.y,e1, fmaf(vo.z,e2, fmaf(vo.w,e3, ao))));
                ac = fmaf(vc.x,e0, fmaf(vc.y,e1, fmaf(vc.z,e2, fmaf(vc.w,e3, ac))));
            }
            float ig = 1.f / (1.f + expf(-(ai + b_i[hh])));
            float fg = 1.f / (1.f + expf(-(af + b_f[hh])));
            float og = 1.f / (1.f + expf(-(ao + b_o[hh])));
            float cg = tanhf(ac + b_c[hh]);
            float cn = fg * g_c[b*NH + hh] + ig * cg;   // g_c touched only by this thread
            g_c[b*NH + hh] = cn;
            g_h[b*NH + hh] = og * tanhf(cn);
        }
        grid_sync(gen);
    }
}

// ---------------- launch ----------------
extern "C" void kernel_launch(void* const* d_in, const int* in_sizes, int n_in,
                              void* d_out, int out_size)
{
    const float* x       = (const float*)d_in[0];
    const float* xmean   = (const float*)d_in[1];
    const int*   clus    = (const int*)  d_in[2];   // int32 or int64 payload, auto-detected
    const float* W_i     = (const float*)d_in[3];
    const float* b_i     = (const float*)d_in[4];
    const float* W_f     = (const float*)d_in[5];
    const float* b_f     = (const float*)d_in[6];
    const float* W_o     = (const float*)d_in[7];
    const float* b_o     = (const float*)d_in[8];
    const float* W_c     = (const float*)d_in[9];
    const float* b_c     = (const float*)d_in[10];
    const float* W_fc    = (const float*)d_in[11];
    const float* b_fc    = (const float*)d_in[12];
    const float* gz_w    = (const float*)d_in[13];
    const float* gz_b    = (const float*)d_in[14];
    const float* gzp_w   = (const float*)d_in[15];
    const float* gzp_b   = (const float*)d_in[16];
    const float* memory  = (const float*)d_in[17];
    const float* local_w = (const float*)d_in[18];
    const float* global_w= (const float*)d_in[19];
    float* out = (float*)d_out;

    // idempotent; if it no-ops during capture, the pre-capture correctness call already set it
    cudaFuncSetAttribute(rnn_kernel, cudaFuncAttributeMaxDynamicSharedMemorySize, SMEM_BYTES);

    prep_kernel<<<512, 256>>>(x, xmean, clus, gz_w, gz_b, gzp_w, gzp_b, memory, local_w);
    rnn_kernel<<<GRID, NTHR, SMEM_BYTES>>>(W_i, b_i, W_f, b_f, W_o, b_o, W_c, b_c,
                                           W_fc, b_fc, memory, global_w, local_w, out);
}

// round 6
// speedup vs baseline: 4.0440x; 4.0440x over previous
#include <cuda_runtime.h>

#define NB 128
#define NT 96
#define ND 256
#define NH 256
#define NCM 512
#define KA 512
#define KC 1280
#define GRID 128
#define NTHR 512

#define AC_STRIDE 1284
#define SMEM_FLOATS (16 * AC_STRIDE)
#define SMEM_BYTES  (SMEM_FLOATS * 4)   // 82176 bytes

// phase A smem offsets (floats)
#define A_ACT    0
#define A_STRIDE 516
#define A_PART   (8 * A_STRIDE)          // partials: 512 slots * 5-pad
#define A_SCORE  (A_PART + 2560)

// ---------------- static device scratch ----------------
__device__ float g_Z   [NB*NT*ND];
__device__ float g_ZP  [NB*NT*ND];
__device__ float g_LP  [NB*NT*ND];
__device__ float g_hall[(NT+1)*NB*NH];
__device__ float g_c   [NB*NH];
__device__ float g_sw  [NB*NCM];
__device__ float g_mm  [NCM*ND];
__device__ float g_memT[ND*NCM];
__device__ float g_W4r [4*NH*KC];     // row-major folded gate weights
__device__ float g_W4q [4*NH*KC];     // blocked [g][k4][hh][4]
__device__ float g_b4  [4*NH];
__device__ float g_Wscr[NCM*KA];      // row-major folded score weights
__device__ float g_Wscq[NCM*KA];      // blocked [k4][cm][4]
__device__ float g_csc [NCM];
__device__ unsigned int g_arrive;
__device__ unsigned int g_release;

// NOTE: parameter names must not collide with float4 member tokens x/y/z/w
#define FMA4(ACC, WV, AV) ACC = fmaf((WV).x,(AV).x, fmaf((WV).y,(AV).y, fmaf((WV).z,(AV).z, fmaf((WV).w,(AV).w,(ACC)))))

// ---------------- prep1: z/zp/LP, masked memory, memT, state init ----------------
__global__ void prep1(const float* __restrict__ x, const float* __restrict__ xmean,
                      const int* __restrict__ cl32,
                      const float* __restrict__ gz_w,  const float* __restrict__ gz_b,
                      const float* __restrict__ gzp_w, const float* __restrict__ gzp_b,
                      const float* __restrict__ memory, const float* __restrict__ local_w)
{
    int tid  = blockIdx.x * blockDim.x + threadIdx.x;
    int nthr = gridDim.x * blockDim.x;
    bool is64 = (cl32[1] == 0);   // cluster vals are 1..8 -> int64 high word of elem0 is 0

    for (int i = tid; i < NB*NT*ND; i += nthr) {
        int d = i & (ND - 1);
        int t = (i / ND) % NT;
        int b = i / (ND * NT);
        long long o = (((long long)b * 6) * NT + t) * ND + d;
        float xt  = x[o];
        float xl  = x[o + 1ll*NT*ND];
        float mk  = x[o + 2ll*NT*ND];
        float dt  = x[o + 3ll*NT*ND];
        float xlb = x[o + 4ll*NT*ND];
        float dtb = x[o + 5ll*NT*ND];
        float mean = xmean[t*ND + d];
        float dz  = expf(-fmaxf(dt  * gz_w[d]  + gz_b[d],  0.f));
        float dzp = expf(-fmaxf(dtb * gzp_w[d] + gzp_b[d], 0.f));
        float z  = mk*xt + (1.f - mk)*(dz *xl  + (1.f - dz )*mean);
        float zp = mk*xt + (1.f - mk)*(dzp*xlb + (1.f - dzp)*mean);
        g_Z[i]  = z;
        g_ZP[i] = zp;
        g_LP[i] = local_w[d]*z + local_w[ND + d]*zp;
    }
    for (int i = tid; i < NCM*ND; i += nthr) {
        int d  = i & (ND - 1);
        int c  = i / (64 * ND);
        int cv = is64 ? cl32[2*d] : cl32[d];
        g_mm[i] = (cv == c + 1) ? memory[i] : 0.f;
    }
    for (int i = tid; i < ND*NCM; i += nthr) {
        int d = i / NCM, cm = i % NCM;
        g_memT[i] = memory[cm*ND + d];
    }
    for (int i = tid; i < NB*NH; i += nthr) { g_hall[i] = 0.f; g_c[i] = 0.f; }
    if (tid == 0) { g_arrive = 0u; g_release = 0u; }
}

// ---------------- prep2: folded score weights (row-major) + csc ----------------
// scores[b,cm] = mm[cm,:].LP(t)  +  h . Wsc2[cm,:]  +  csc[cm]
__global__ void prep2(const float* __restrict__ W_fc, const float* __restrict__ b_fc,
                      const float* __restrict__ local_w)
{
    __shared__ float A[16*256];
    int cmt = blockIdx.x;            // 0..31 (16 cm rows each)
    int tid = threadIdx.x;           // 512
    for (int idx = tid; idx < 16*256; idx += 512) {
        int ci = idx >> 8, d = idx & 255;
        float mmv = g_mm[(cmt*16 + ci)*ND + d];
        A[idx] = local_w[2*ND + d] * mmv;
        g_Wscr[(cmt*16 + ci)*KA + d] = mmv;
    }
    __syncthreads();
    int j = tid & 255, half = tid >> 8;
    float acc[8];
    #pragma unroll
    for (int i = 0; i < 8; ++i) acc[i] = 0.f;
    for (int d = 0; d < 256; ++d) {
        float wf = W_fc[d*ND + j];
        #pragma unroll
        for (int i = 0; i < 8; ++i) acc[i] = fmaf(A[(half*8+i)*256 + d], wf, acc[i]);
    }
    #pragma unroll
    for (int i = 0; i < 8; ++i)
        g_Wscr[(cmt*16 + half*8 + i)*KA + 256 + j] = acc[i];
    if (tid < 16) {
        float s = 0.f;
        for (int d = 0; d < 256; ++d) s += A[tid*256 + d] * b_fc[d];
        g_csc[cmt*16 + tid] = s;
    }
}

// ---------------- prep3: folded gate weights (row-major) + folded bias ----------------
// new K layout: [0:512)=z,zp (verbatim), [512:1024)=s' (gd fold), [1024:1280)=h (+ x_i fold)
__global__ void prep3(const float* __restrict__ W_i, const float* __restrict__ W_f,
                      const float* __restrict__ W_o, const float* __restrict__ W_c,
                      const float* __restrict__ b_i, const float* __restrict__ b_f,
                      const float* __restrict__ b_o, const float* __restrict__ b_c,
                      const float* __restrict__ W_fc, const float* __restrict__ b_fc)
{
    __shared__ float A1[16*256];   // gd segment  (orig cols 768:1024)
    __shared__ float A2[16*256];   // x_i segment (orig cols 512:768)
    int g = blockIdx.x >> 4, hht = blockIdx.x & 15;
    const float* Wg = (g == 0) ? W_i : (g == 1) ? W_f : (g == 2) ? W_o : W_c;
    const float* bg = (g == 0) ? b_i : (g == 1) ? b_f : (g == 2) ? b_o : b_c;
    int tid = threadIdx.x;   // 512

    for (int idx = tid; idx < 16*256; idx += 512) {
        int hi = idx >> 8, d = idx & 255;
        int row = hht*16 + hi;
        A1[idx] = Wg[row*KC + 768 + d];
        A2[idx] = Wg[row*KC + 512 + d];
    }
    for (int idx = tid; idx < 16*512; idx += 512) {     // z,zp segments copied verbatim
        int hi = idx >> 9, k = idx & 511;
        int row = hht*16 + hi;
        g_W4r[(g*NH + row)*KC + k] = Wg[row*KC + k];
    }
    __syncthreads();
    {   // h segment: W[hh,1024+j] + sum_d A2[hh,d]*W_fc[d,j]
        int j = tid & 255, half = tid >> 8;
        float acc[8];
        #pragma unroll
        for (int i = 0; i < 8; ++i) acc[i] = 0.f;
        for (int d = 0; d < 256; ++d) {
            float wf = W_fc[d*ND + j];
            #pragma unroll
            for (int i = 0; i < 8; ++i) acc[i] = fmaf(A2[(half*8+i)*256 + d], wf, acc[i]);
        }
        #pragma unroll
        for (int i = 0; i < 8; ++i) {
            int hhr = hht*16 + half*8 + i;
            g_W4r[(g*NH + hhr)*KC + 1024 + j] = Wg[hhr*KC + 1024 + j] + acc[i];
        }
    }
    {   // s' segment: Wg2[hh,cm] = sum_d A1[hh,d]*mem[cm,d]
        int cm = tid;
        float acc[16];
        #pragma unroll
        for (int i = 0; i < 16; ++i) acc[i] = 0.f;
        for (int d = 0; d < 256; ++d) {
            float mt = g_memT[d*NCM + cm];
            #pragma unroll
            for (int i = 0; i < 16; ++i) acc[i] = fmaf(A1[i*256 + d], mt, acc[i]);
        }
        #pragma unroll
        for (int i = 0; i < 16; ++i)
            g_W4r[(g*NH + hht*16 + i)*KC + 512 + cm] = acc[i];
    }
    if (tid < 16) {   // bias fold: + sum_d A2[hh,d]*b_fc[d]
        float s = 0.f;
        for (int d = 0; d < 256; ++d) s += A2[tid*256 + d] * b_fc[d];
        g_b4[g*NH + hht*16 + tid] = bg[hht*16 + tid] + s;
    }
}

// ---------------- prep4: transpose to blocked (coalesced-LDG) layouts ----------------
__global__ void prep4()
{
    int idx = blockIdx.x * blockDim.x + threadIdx.x;
    if (idx < 4*320*256) {               // g_W4q[((g*320+k4)*256+hh)*4]
        int hh = idx & 255;
        int gk = idx >> 8;
        int g = gk / 320, k4 = gk % 320;
        *(float4*)&g_W4q[idx*4] = *(const float4*)&g_W4r[(g*NH + hh)*KC + k4*4];
    }
    int j = idx - 4*320*256;
    if (j >= 0 && j < 128*512) {         // g_Wscq[(k4*512+cm)*4]
        int cm = j & 511, k4 = j >> 9;
        *(float4*)&g_Wscq[j*4] = *(const float4*)&g_Wscr[cm*KA + k4*4];
    }
}

// ---------------- grid barrier (tight spin; counters reset by prep1) ----------------
__device__ __forceinline__ void grid_sync(unsigned int& gen)
{
    __syncthreads();
    if (threadIdx.x == 0) {
        __threadfence();
        unsigned int target = gen + 1u;
        unsigned int a = atomicAdd(&g_arrive, 1u) + 1u;
        if (a == target * GRID) {
            atomicExch(&g_release, target);
        } else {
            volatile unsigned int* rel = &g_release;
            while (*rel < target) { }
        }
        __threadfence();
    }
    gen += 1u;
    __syncthreads();
}

// ---------------- persistent recurrence: 96 x (scores+softmax -> gates) ----------------
__global__ void __launch_bounds__(NTHR, 1)
rnn_kernel(const float* __restrict__ global_w)
{
    extern __shared__ float sm[];
    const int cta = blockIdx.x, tid = threadIdx.x;
    const int lane = tid & 31, wid = tid >> 5;
    // phase A ids: CTA = (bgrp:16 x 8 batches, ccl:8 x 64 cm); thread = (a_ml:64, a_bh:2, a_ks:4)
    const int bgrp = cta >> 3, ccl = cta & 7;
    const int a_ml = tid & 63, a_bh = (tid >> 6) & 1, a_ks = tid >> 7;
    // phase C ids: CTA = (bg:8 x 16 batches, sub:16 x 16 hh); thread = (c_hl:16, c_bq:4, c_ks:8)
    const int bg = cta >> 4, sub = cta & 15;
    const int c_hl = tid & 15, c_bq = (tid >> 4) & 3, c_ks = tid >> 6;
    const int hh = sub*16 + c_hl;
    unsigned int gen = 0;

    for (int t = 0; t < NT; ++t) {
        // ===== Phase A: scores + softmax -> s'(t) in g_sw =====
        {
            for (int idx = tid; idx < 8*128; idx += NTHR) {   // stage [8b][512k] acts
                int bi = idx >> 7, k4 = idx & 127;
                int b = bgrp*8 + bi;
                float4 v;
                if (k4 < 64) v = *(const float4*)&g_LP[((b*NT + t) << 8) + k4*4];
                else         v = __ldcg((const float4*)&g_hall[((t*NB + b) << 8) + (k4-64)*4]);
                *(float4*)&sm[A_ACT + bi*A_STRIDE + k4*4] = v;
            }
            __syncthreads();
            float acc[4] = {0.f, 0.f, 0.f, 0.f};
            {
                const float4* wp = (const float4*)g_Wscq + (a_ks*32)*NCM + (ccl*64 + a_ml);
                const float*  ap = sm + A_ACT + (a_bh*4)*A_STRIDE + a_ks*128;
                #pragma unroll 4
                for (int it = 0; it < 32; ++it) {
                    float4 wv = wp[it*NCM];
                    int k = it*4;
                    #pragma unroll
                    for (int j = 0; j < 4; ++j) {
                        float4 av = *(const float4*)(ap + j*A_STRIDE + k);
                        FMA4(acc[j], wv, av);
                    }
                }
            }
            {
                int base = A_PART + ((a_ks*64 + a_ml)*2 + a_bh)*5;
                #pragma unroll
                for (int j = 0; j < 4; ++j) sm[base + j] = acc[j];
            }
            __syncthreads();
            {   // reduce over a_ks + csc bias; bl encodes (bh=bl>>2, j=bl&3) -> batch bl
                int bl = tid >> 6, m = tid & 63;
                float s = g_csc[ccl*64 + m];
                #pragma unroll
                for (int ks = 0; ks < 4; ++ks)
                    s += sm[A_PART + ((ks*64 + m)*2 + (bl >> 2))*5 + (bl & 3)];
                sm[A_SCORE + bl*64 + m] = s;
            }
            __syncthreads();
            if (wid < 8) {   // softmax over 64 m for batch wid; scale by global_w[ccl]
                float v0 = sm[A_SCORE + wid*64 + lane];
                float v1 = sm[A_SCORE + wid*64 + 32 + lane];
                float mx = fmaxf(v0, v1);
                #pragma unroll
                for (int o = 16; o; o >>= 1) mx = fmaxf(mx, __shfl_xor_sync(0xffffffffu, mx, o));
                float e0 = expf(v0 - mx), e1 = expf(v1 - mx);
                float s = e0 + e1;
                #pragma unroll
                for (int o = 16; o; o >>= 1) s += __shfl_xor_sync(0xffffffffu, s, o);
                float sc = global_w[ccl] / s;
                int b = bgrp*8 + wid;
                __stcg(&g_sw[b*NCM + ccl*64 + lane],      e0*sc);
                __stcg(&g_sw[b*NCM + ccl*64 + 32 + lane], e1*sc);
            }
        }
        grid_sync(gen);

        // ===== Phase C: 4-gate GEMM over K=1280 [z,zp,s',h]; update c,h =====
        {
            for (int idx = tid; idx < 16*320; idx += NTHR) {   // stage [16b][1280k] acts
                int bi = idx / 320, k = (idx % 320) * 4;
                int b = bg*16 + bi;
                float4 v;
                if      (k < 256)  v = *(const float4*)&g_Z [((b*NT + t) << 8) + k];
                else if (k < 512)  v = *(const float4*)&g_ZP[((b*NT + t) << 8) + (k - 256)];
                else if (k < 1024) v = __ldcg((const float4*)&g_sw[(b << 9) + (k - 512)]);
                else               v = __ldcg((const float4*)&g_hall[((t*NB + b) << 8) + (k - 1024)]);
                *(float4*)&sm[bi*AC_STRIDE + k] = v;
            }
            __syncthreads();
            float acc[16];
            #pragma unroll
            for (int i = 0; i < 16; ++i) acc[i] = 0.f;
            {
                const int k40 = c_ks * 40;
                const float4* w0 = (const float4*)g_W4q + ((0*320 + k40)*NH + hh);
                const float4* w1 = (const float4*)g_W4q + ((1*320 + k40)*NH + hh);
                const float4* w2 = (const float4*)g_W4q + ((2*320 + k40)*NH + hh);
                const float4* w3 = (const float4*)g_W4q + ((3*320 + k40)*NH + hh);
                const float*  ap = sm + (c_bq*4)*AC_STRIDE + c_ks*160;
                #pragma unroll 2
                for (int it = 0; it < 40; ++it) {
                    float4 wva = w0[it*NH];
                    float4 wvb = w1[it*NH];
                    float4 wvc = w2[it*NH];
                    float4 wvd = w3[it*NH];
                    int k = it*4;
                    #pragma unroll
                    for (int j = 0; j < 4; ++j) {
                        float4 av = *(const float4*)(ap + j*AC_STRIDE + k);
                        FMA4(acc[0*4+j], wva, av);
                        FMA4(acc[1*4+j], wvb, av);
                        FMA4(acc[2*4+j], wvc, av);
                        FMA4(acc[3*4+j], wvd, av);
                    }
                }
            }
            __syncthreads();                         // act region reused for partials
            {
                int base = (c_ks*64 + c_bq*16 + c_hl)*17;   // pad-17: conflict-free
                #pragma unroll
                for (int v = 0; v < 16; ++v) sm[base + v] = acc[v];
            }
            __syncthreads();
            if (tid < 256) {   // (hl2:16, bi:16): reduce 8 ks, gates, state update
                int hl2 = tid & 15, bi = tid >> 4;
                int bq = bi >> 2, j = bi & 3;
                int b = bg*16 + bi, h2 = sub*16 + hl2;
                float gg[4];
                #pragma unroll
                for (int g = 0; g < 4; ++g) {
                    float s = g_b4[g*NH + h2];
                    #pragma unroll
                    for (int ks = 0; ks < 8; ++ks)
                        s += sm[(ks*64 + bq*16 + hl2)*17 + g*4 + j];
                    gg[g] = s;
                }
                float ig = 1.f / (1.f + expf(-gg[0]));
                float fg = 1.f / (1.f + expf(-gg[1]));
                float og = 1.f / (1.f + expf(-gg[2]));
                float cg = tanhf(gg[3]);
                float cn = fg * g_c[b*NH + h2] + ig * cg;
                g_c[b*NH + h2] = cn;
                __stcg(&g_hall[(((t+1)*NB + b) << 8) + h2], og * tanhf(cn));
            }
        }
        grid_sync(gen);
    }
}

// ---------------- final: out[b,t,:] = h_{t+1} @ W_fc^T + b_fc ----------------
__global__ void out_gemm(const float* __restrict__ W_fc, const float* __restrict__ b_fc,
                         float* __restrict__ out)
{
    __shared__ float sa[16*256];     // 16 KB
    int rt = blockIdx.x >> 2, dt = blockIdx.x & 3;
    int tid = threadIdx.x;           // 256
    int r0 = rt * 16;
    for (int idx = tid; idx < 16*64; idx += 256) {
        int row = idx >> 6, k4 = idx & 63;
        int r = r0 + row, b = r / NT, t = r % NT;
        *(float4*)&sa[row*256 + k4*4] =
            *(const float4*)&g_hall[(((t+1)*NB + b) << 8) + k4*4];
    }
    __syncthreads();
    int dl = tid & 63, rl = tid >> 6;   // rl: 4 groups x 4 rows
    int d = dt*64 + dl;
    float acc[4];
    #pragma unroll
    for (int i = 0; i < 4; ++i) acc[i] = 0.f;
    const float* wrow = W_fc + d*NH;
    #pragma unroll 4
    for (int k4 = 0; k4 < 64; ++k4) {
        float4 wv = *(const float4*)(wrow + k4*4);
        #pragma unroll
        for (int i = 0; i < 4; ++i) {
            float4 av = *(const float4*)&sa[(rl*4 + i)*256 + k4*4];
            FMA4(acc[i], wv, av);
        }
    }
    float bb = b_fc[d];
    #pragma unroll
    for (int i = 0; i < 4; ++i)
        out[(r0 + rl*4 + i)*ND + d] = acc[i] + bb;
}

// ---------------- launch ----------------
extern "C" void kernel_launch(void* const* d_in, const int* in_sizes, int n_in,
                              void* d_out, int out_size)
{
    const float* x        = (const float*)d_in[0];
    const float* xmean    = (const float*)d_in[1];
    const int*   clus     = (const int*)  d_in[2];
    const float* W_i      = (const float*)d_in[3];
    const float* b_i      = (const float*)d_in[4];
    const float* W_f      = (const float*)d_in[5];
    const float* b_f      = (const float*)d_in[6];
    const float* W_o      = (const float*)d_in[7];
    const float* b_o      = (const float*)d_in[8];
    const float* W_c      = (const float*)d_in[9];
    const float* b_c      = (const float*)d_in[10];
    const float* W_fc     = (const float*)d_in[11];
    const float* b_fc     = (const float*)d_in[12];
    const float* gz_w     = (const float*)d_in[13];
    const float* gz_b     = (const float*)d_in[14];
    const float* gzp_w    = (const float*)d_in[15];
    const float* gzp_b    = (const float*)d_in[16];
    const float* memory   = (const float*)d_in[17];
    const float* local_w  = (const float*)d_in[18];
    const float* global_w = (const float*)d_in[19];
    float* out = (float*)d_out;

    cudaFuncSetAttribute(rnn_kernel, cudaFuncAttributeMaxDynamicSharedMemorySize, SMEM_BYTES);

    prep1<<<512, 256>>>(x, xmean, clus, gz_w, gz_b, gzp_w, gzp_b, memory, local_w);
    prep2<<<32, 512>>>(W_fc, b_fc, local_w);
    prep3<<<64, 512>>>(W_i, W_f, W_o, W_c, b_i, b_f, b_o, b_c, W_fc, b_fc);
    prep4<<<1536, 256>>>();
    rnn_kernel<<<GRID, NTHR, SMEM_BYTES>>>(global_w);
    out_gemm<<<3072, 256>>>(W_fc, b_fc, out);
}

// round 7
// speedup vs baseline: 4.2684x; 1.0555x over previous
#include <cuda_runtime.h>

#define NB 128
#define NT 96
#define ND 256
#define NH 256
#define NCM 512
#define KA 512
#define KC 1280
#define GRID 128
#define NTHR 512
#define NGRP 8            // 8 independent groups x 16 CTAs x 16 batches

// smem layout (floats): disjoint C and A regions so staging can overlap barriers
#define AC_STRIDE 1284
#define C_ACT    0
#define A_ACT    (16 * AC_STRIDE)        // 20544
#define A_STRIDE 516
#define A_PART   (A_ACT + 8 * A_STRIDE)  // 24672 (512 slots * 5-pad = 2560)
#define A_SCORE  (A_PART + 2560)         // 27232 (+512)
#define SMEM_FLOATS (A_SCORE + 512)      // 27744
#define SMEM_BYTES  (SMEM_FLOATS * 4)    // 110976 B

// ---------------- static device scratch ----------------
__device__ float g_Z   [NB*NT*ND];
__device__ float g_ZP  [NB*NT*ND];
__device__ float g_LP  [NB*NT*ND];
__device__ float g_hall[(NT+1)*NB*NH];
__device__ float g_c   [NB*NH];
__device__ float g_sw  [NB*NCM];
__device__ float g_mm  [NCM*ND];
__device__ float g_memT[ND*NCM];
__device__ float g_W4r [4*NH*KC];     // row-major folded gate weights
__device__ float g_W4q [4*NH*KC];     // blocked [g][k4][hh][4]
__device__ float g_b4  [4*NH];
__device__ float g_Wscr[NCM*KA];      // row-major folded score weights
__device__ float g_Wscq[NCM*KA];      // blocked [k4][cm][4]
__device__ float g_csc [NCM];
__device__ unsigned int g_garrive [NGRP*64];   // 256B-strided per-group counters
__device__ unsigned int g_grelease[NGRP*64];

// parameter names must not collide with float4 member tokens x/y/z/w
#define FMA4(ACC, WV, AV) ACC = fmaf((WV).x,(AV).x, fmaf((WV).y,(AV).y, fmaf((WV).z,(AV).z, fmaf((WV).w,(AV).w,(ACC)))))

// ---------------- prep1: z/zp/LP, masked memory, memT, state + barrier init ----------------
__global__ void prep1(const float* __restrict__ x, const float* __restrict__ xmean,
                      const int* __restrict__ cl32,
                      const float* __restrict__ gz_w,  const float* __restrict__ gz_b,
                      const float* __restrict__ gzp_w, const float* __restrict__ gzp_b,
                      const float* __restrict__ memory, const float* __restrict__ local_w)
{
    int tid  = blockIdx.x * blockDim.x + threadIdx.x;
    int nthr = gridDim.x * blockDim.x;
    bool is64 = (cl32[1] == 0);   // cluster vals are 1..8 -> int64 high word of elem0 is 0

    for (int i = tid; i < NB*NT*ND; i += nthr) {
        int d = i & (ND - 1);
        int t = (i / ND) % NT;
        int b = i / (ND * NT);
        long long o = (((long long)b * 6) * NT + t) * ND + d;
        float xt  = x[o];
        float xl  = x[o + 1ll*NT*ND];
        float mk  = x[o + 2ll*NT*ND];
        float dt  = x[o + 3ll*NT*ND];
        float xlb = x[o + 4ll*NT*ND];
        float dtb = x[o + 5ll*NT*ND];
        float mean = xmean[t*ND + d];
        float dz  = expf(-fmaxf(dt  * gz_w[d]  + gz_b[d],  0.f));
        float dzp = expf(-fmaxf(dtb * gzp_w[d] + gzp_b[d], 0.f));
        float z  = mk*xt + (1.f - mk)*(dz *xl  + (1.f - dz )*mean);
        float zp = mk*xt + (1.f - mk)*(dzp*xlb + (1.f - dzp)*mean);
        g_Z[i]  = z;
        g_ZP[i] = zp;
        g_LP[i] = local_w[d]*z + local_w[ND + d]*zp;
    }
    for (int i = tid; i < NCM*ND; i += nthr) {
        int d  = i & (ND - 1);
        int c  = i / (64 * ND);
        int cv = is64 ? cl32[2*d] : cl32[d];
        g_mm[i] = (cv == c + 1) ? memory[i] : 0.f;
    }
    for (int i = tid; i < ND*NCM; i += nthr) {
        int d = i / NCM, cm = i % NCM;
        g_memT[i] = memory[cm*ND + d];
    }
    for (int i = tid; i < NB*NH; i += nthr) { g_hall[i] = 0.f; g_c[i] = 0.f; }
    if (tid < NGRP*64) { g_garrive[tid] = 0u; g_grelease[tid] = 0u; }
}

// ---------------- prep2: folded score weights (row-major) + csc ----------------
__global__ void prep2(const float* __restrict__ W_fc, const float* __restrict__ b_fc,
                      const float* __restrict__ local_w)
{
    __shared__ float A[16*256];
    int cmt = blockIdx.x;            // 0..31 (16 cm rows each)
    int tid = threadIdx.x;           // 512
    for (int idx = tid; idx < 16*256; idx += 512) {
        int ci = idx >> 8, d = idx & 255;
        float mmv = g_mm[(cmt*16 + ci)*ND + d];
        A[idx] = local_w[2*ND + d] * mmv;
        g_Wscr[(cmt*16 + ci)*KA + d] = mmv;
    }
    __syncthreads();
    int j = tid & 255, half = tid >> 8;
    float acc[8];
    #pragma unroll
    for (int i = 0; i < 8; ++i) acc[i] = 0.f;
    for (int d = 0; d < 256; ++d) {
        float wf = W_fc[d*ND + j];
        #pragma unroll
        for (int i = 0; i < 8; ++i) acc[i] = fmaf(A[(half*8+i)*256 + d], wf, acc[i]);
    }
    #pragma unroll
    for (int i = 0; i < 8; ++i)
        g_Wscr[(cmt*16 + half*8 + i)*KA + 256 + j] = acc[i];
    if (tid < 16) {
        float s = 0.f;
        for (int d = 0; d < 256; ++d) s += A[tid*256 + d] * b_fc[d];
        g_csc[cmt*16 + tid] = s;
    }
}

// ---------------- prep3: folded gate weights (row-major) + folded bias ----------------
// new K layout: [0:512)=z,zp, [512:1024)=s' (gd fold), [1024:1280)=h (+ x_i fold)
__global__ void prep3(const float* __restrict__ W_i, const float* __restrict__ W_f,
                      const float* __restrict__ W_o, const float* __restrict__ W_c,
                      const float* __restrict__ b_i, const float* __restrict__ b_f,
                      const float* __restrict__ b_o, const float* __restrict__ b_c,
                      const float* __restrict__ W_fc, const float* __restrict__ b_fc)
{
    __shared__ float A1[16*256];   // gd segment  (orig cols 768:1024)
    __shared__ float A2[16*256];   // x_i segment (orig cols 512:768)
    int g = blockIdx.x >> 4, hht = blockIdx.x & 15;
    const float* Wg = (g == 0) ? W_i : (g == 1) ? W_f : (g == 2) ? W_o : W_c;
    const float* bg = (g == 0) ? b_i : (g == 1) ? b_f : (g == 2) ? b_o : b_c;
    int tid = threadIdx.x;   // 512

    for (int idx = tid; idx < 16*256; idx += 512) {
        int hi = idx >> 8, d = idx & 255;
        int row = hht*16 + hi;
        A1[idx] = Wg[row*KC + 768 + d];
        A2[idx] = Wg[row*KC + 512 + d];
    }
    for (int idx = tid; idx < 16*512; idx += 512) {     // z,zp segments verbatim
        int hi = idx >> 9, k = idx & 511;
        int row = hht*16 + hi;
        g_W4r[(g*NH + row)*KC + k] = Wg[row*KC + k];
    }
    __syncthreads();
    {   // h segment: W[hh,1024+j] + sum_d A2[hh,d]*W_fc[d,j]
        int j = tid & 255, half = tid >> 8;
        float acc[8];
        #pragma unroll
        for (int i = 0; i < 8; ++i) acc[i] = 0.f;
        for (int d = 0; d < 256; ++d) {
            float wf = W_fc[d*ND + j];
            #pragma unroll
            for (int i = 0; i < 8; ++i) acc[i] = fmaf(A2[(half*8+i)*256 + d], wf, acc[i]);
        }
        #pragma unroll
        for (int i = 0; i < 8; ++i) {
            int hhr = hht*16 + half*8 + i;
            g_W4r[(g*NH + hhr)*KC + 1024 + j] = Wg[hhr*KC + 1024 + j] + acc[i];
        }
    }
    {   // s' segment: Wg2[hh,cm] = sum_d A1[hh,d]*mem[cm,d]
        int cm = tid;
        float acc[16];
        #pragma unroll
        for (int i = 0; i < 16; ++i) acc[i] = 0.f;
        for (int d = 0; d < 256; ++d) {
            float mt = g_memT[d*NCM + cm];
            #pragma unroll
            for (int i = 0; i < 16; ++i) acc[i] = fmaf(A1[i*256 + d], mt, acc[i]);
        }
        #pragma unroll
        for (int i = 0; i < 16; ++i)
            g_W4r[(g*NH + hht*16 + i)*KC + 512 + cm] = acc[i];
    }
    if (tid < 16) {   // bias fold
        float s = 0.f;
        for (int d = 0; d < 256; ++d) s += A2[tid*256 + d] * b_fc[d];
        g_b4[g*NH + hht*16 + tid] = bg[hht*16 + tid] + s;
    }
}

// ---------------- prep4: blocked (coalesced-LDG) layouts ----------------
__global__ void prep4()
{
    int idx = blockIdx.x * blockDim.x + threadIdx.x;
    if (idx < 4*320*256) {               // g_W4q[((g*320+k4)*256+hh)*4]
        int hh = idx & 255;
        int gk = idx >> 8;
        int g = gk / 320, k4 = gk % 320;
        *(float4*)&g_W4q[idx*4] = *(const float4*)&g_W4r[(g*NH + hh)*KC + k4*4];
    }
    int j = idx - 4*320*256;
    if (j >= 0 && j < 128*512) {         // g_Wscq[(k4*512+cm)*4]
        int cm = j & 511, k4 = j >> 9;
        *(float4*)&g_Wscq[j*4] = *(const float4*)&g_Wscr[cm*KA + k4*4];
    }
}

// ---------------- per-group barrier (16 CTAs; monotonic; reset by prep1) ----------------
__device__ __forceinline__ void group_sync(int grp, unsigned int& gen)
{
    __syncthreads();
    if (threadIdx.x == 0) {
        __threadfence();
        unsigned int target = gen + 1u;
        unsigned int a = atomicAdd(&g_garrive[grp*64], 1u) + 1u;
        if (a == target * 16u) {
            atomicExch(&g_grelease[grp*64], target);
        } else {
            volatile unsigned int* rel = &g_grelease[grp*64];
            while (*rel < target) { }
        }
        __threadfence();
    }
    gen += 1u;
    __syncthreads();
}

// ---------------- persistent recurrence: 8 independent groups ----------------
__global__ void __launch_bounds__(NTHR, 1)
rnn_kernel(const float* __restrict__ global_w)
{
    extern __shared__ float sm[];
    const int cta = blockIdx.x, tid = threadIdx.x;
    const int lane = tid & 31, wid = tid >> 5;
    const int grp = cta >> 4, local = cta & 15;
    // phase A ids: local = (bhalf:2 x 8 batches, ccl:8 clusters); thread = (a_ml:64, a_bh:2, a_ks:4)
    const int bhalf = local >> 3, ccl = local & 7;
    const int a_b0 = grp*16 + bhalf*8;
    const int a_ml = tid & 63, a_bh = (tid >> 6) & 1, a_ks = tid >> 7;
    // phase C ids: local = sub (16 hh slice); 16 batches = grp*16..; thread = (c_hl:16, c_bq:4, c_ks:8)
    const int sub = local;
    const int c_b0 = grp*16;
    const int c_hl = tid & 15, c_bq = (tid >> 4) & 3, c_ks = tid >> 6;
    const int hh = sub*16 + c_hl;
    unsigned int gen = 0;

    // pre-stage A acts for t=0: LP(0) and h(0)
    for (int idx = tid; idx < 8*128; idx += NTHR) {
        int bi = idx >> 7, k4 = idx & 127;
        int b = a_b0 + bi;
        float4 v;
        if (k4 < 64) v = *(const float4*)&g_LP[((b*NT + 0) << 8) + k4*4];
        else         v = __ldcg((const float4*)&g_hall[(b << 8) + (k4-64)*4]);
        *(float4*)&sm[A_ACT + bi*A_STRIDE + k4*4] = v;
    }
    __syncthreads();

    for (int t = 0; t < NT; ++t) {
        // ===== Phase A: scores + softmax -> s'(t) in g_sw =====
        {
            float acc[4] = {0.f, 0.f, 0.f, 0.f};
            {
                const float4* wp = (const float4*)g_Wscq + (a_ks*32)*NCM + (ccl*64 + a_ml);
                const float*  ap = sm + A_ACT + (a_bh*4)*A_STRIDE + a_ks*128;
                #pragma unroll 4
                for (int it = 0; it < 32; ++it) {
                    float4 wv = wp[it*NCM];
                    int k = it*4;
                    #pragma unroll
                    for (int j = 0; j < 4; ++j) {
                        float4 av = *(const float4*)(ap + j*A_STRIDE + k);
                        FMA4(acc[j], wv, av);
                    }
                }
            }
            {
                int base = A_PART + ((a_ks*64 + a_ml)*2 + a_bh)*5;
                #pragma unroll
                for (int j = 0; j < 4; ++j) sm[base + j] = acc[j];
            }
            __syncthreads();
            {   // reduce over a_ks + csc bias; bl = batch index (bh=bl>>2, j=bl&3)
                int bl = tid >> 6, m = tid & 63;
                float s = g_csc[ccl*64 + m];
                #pragma unroll
                for (int ks = 0; ks < 4; ++ks)
                    s += sm[A_PART + ((ks*64 + m)*2 + (bl >> 2))*5 + (bl & 3)];
                sm[A_SCORE + bl*64 + m] = s;
            }
            __syncthreads();
            if (wid < 8) {   // softmax over 64 m for batch wid; scale by global_w[ccl]
                float v0 = sm[A_SCORE + wid*64 + lane];
                float v1 = sm[A_SCORE + wid*64 + 32 + lane];
                float mx = fmaxf(v0, v1);
                #pragma unroll
                for (int o = 16; o; o >>= 1) mx = fmaxf(mx, __shfl_xor_sync(0xffffffffu, mx, o));
                float e0 = expf(v0 - mx), e1 = expf(v1 - mx);
                float s = e0 + e1;
                #pragma unroll
                for (int o = 16; o; o >>= 1) s += __shfl_xor_sync(0xffffffffu, s, o);
                float sc = global_w[ccl] / s;
                int b = a_b0 + wid;
                __stcg(&g_sw[b*NCM + ccl*64 + lane],      e0*sc);
                __stcg(&g_sw[b*NCM + ccl*64 + 32 + lane], e1*sc);
            }
        }

        // stage C z/zp(t) (h-independent) BEFORE the barrier
        for (int idx = tid; idx < 16*128; idx += NTHR) {
            int bi = idx >> 7, k = (idx & 127) * 4;
            int b = c_b0 + bi;
            float4 v;
            if (k < 256) v = *(const float4*)&g_Z [((b*NT + t) << 8) + k];
            else         v = *(const float4*)&g_ZP[((b*NT + t) << 8) + (k - 256)];
            *(float4*)&sm[bi*AC_STRIDE + k] = v;
        }
        group_sync(grp, gen);        // group's g_sw complete

        // stage C s'(t) + h(t)
        for (int idx = tid; idx < 16*192; idx += NTHR) {
            int bi = idx / 192, k = 512 + (idx % 192) * 4;
            int b = c_b0 + bi;
            float4 v;
            if (k < 1024) v = __ldcg((const float4*)&g_sw[(b << 9) + (k - 512)]);
            else          v = __ldcg((const float4*)&g_hall[((t*NB + b) << 8) + (k - 1024)]);
            *(float4*)&sm[bi*AC_STRIDE + k] = v;
        }
        __syncthreads();

        // ===== Phase C: 4-gate GEMM over K=1280 [z,zp,s',h]; update c,h =====
        {
            float acc[16];
            #pragma unroll
            for (int i = 0; i < 16; ++i) acc[i] = 0.f;
            {
                const int k40 = c_ks * 40;
                const float4* w0 = (const float4*)g_W4q + ((0*320 + k40)*NH + hh);
                const float4* w1 = (const float4*)g_W4q + ((1*320 + k40)*NH + hh);
                const float4* w2 = (const float4*)g_W4q + ((2*320 + k40)*NH + hh);
                const float4* w3 = (const float4*)g_W4q + ((3*320 + k40)*NH + hh);
                const float*  ap = sm + (c_bq*4)*AC_STRIDE + c_ks*160;
                #pragma unroll 2
                for (int it = 0; it < 40; ++it) {
                    float4 wva = w0[it*NH];
                    float4 wvb = w1[it*NH];
                    float4 wvc = w2[it*NH];
                    float4 wvd = w3[it*NH];
                    int k = it*4;
                    #pragma unroll
                    for (int j = 0; j < 4; ++j) {
                        float4 av = *(const float4*)(ap + j*AC_STRIDE + k);
                        FMA4(acc[0*4+j], wva, av);
                        FMA4(acc[1*4+j], wvb, av);
                        FMA4(acc[2*4+j], wvc, av);
                        FMA4(acc[3*4+j], wvd, av);
                    }
                }
            }
            __syncthreads();                         // act region reused for partials
            {
                int base = (c_ks*64 + c_bq*16 + c_hl)*17;   // pad-17: conflict-free
                #pragma unroll
                for (int v = 0; v < 16; ++v) sm[base + v] = acc[v];
            }
            __syncthreads();
            if (tid < 256) {   // (hl2:16, bi:16): reduce 8 ks, gates, state update
                int hl2 = tid & 15, bi = tid >> 4;
                int bq = bi >> 2, j = bi & 3;
                int b = c_b0 + bi, h2 = sub*16 + hl2;
                float gg[4];
                #pragma unroll
                for (int g = 0; g < 4; ++g) {
                    float s = g_b4[g*NH + h2];
                    #pragma unroll
                    for (int ks = 0; ks < 8; ++ks)
                        s += sm[(ks*64 + bq*16 + hl2)*17 + g*4 + j];
                    gg[g] = s;
                }
                float ig = 1.f / (1.f + expf(-gg[0]));
                float fg = 1.f / (1.f + expf(-gg[1]));
                float og = 1.f / (1.f + expf(-gg[2]));
                float cg = tanhf(gg[3]);
                float cn = fg * g_c[b*NH + h2] + ig * cg;
                g_c[b*NH + h2] = cn;
                __stcg(&g_hall[(((t+1)*NB + b) << 8) + h2], og * tanhf(cn));
            }
        }

        // stage A LP(t+1) (h-independent) BEFORE the barrier
        if (t + 1 < NT) {
            for (int idx = tid; idx < 8*64; idx += NTHR) {
                int bi = idx >> 6, k4 = idx & 63;
                int b = a_b0 + bi;
                *(float4*)&sm[A_ACT + bi*A_STRIDE + k4*4] =
                    *(const float4*)&g_LP[((b*NT + t + 1) << 8) + k4*4];
            }
        }
        group_sync(grp, gen);        // group's h(t+1) complete

        if (t + 1 < NT) {
            for (int idx = tid; idx < 8*64; idx += NTHR) {
                int bi = idx >> 6, k4 = idx & 63;
                int b = a_b0 + bi;
                *(float4*)&sm[A_ACT + bi*A_STRIDE + 256 + k4*4] =
                    __ldcg((const float4*)&g_hall[(((t+1)*NB + b) << 8) + k4*4]);
            }
            __syncthreads();
        }
    }
}

// ---------------- final: out[b,t,:] = h_{t+1} @ W_fc^T + b_fc ----------------
__global__ void out_gemm(const float* __restrict__ W_fc, const float* __restrict__ b_fc,
                         float* __restrict__ out)
{
    __shared__ float sa[16*256];     // 16 KB
    int rt = blockIdx.x >> 2, dt = blockIdx.x & 3;
    int tid = threadIdx.x;           // 256
    int r0 = rt * 16;
    for (int idx = tid; idx < 16*64; idx += 256) {
        int row = idx >> 6, k4 = idx & 63;
        int r = r0 + row, b = r / NT, t = r % NT;
        *(float4*)&sa[row*256 + k4*4] =
            *(const float4*)&g_hall[(((t+1)*NB + b) << 8) + k4*4];
    }
    __syncthreads();
    int dl = tid & 63, rl = tid >> 6;
    int d = dt*64 + dl;
    float acc[4];
    #pragma unroll
    for (int i = 0; i < 4; ++i) acc[i] = 0.f;
    const float* wrow = W_fc + d*NH;
    #pragma unroll 4
    for (int k4 = 0; k4 < 64; ++k4) {
        float4 wv = *(const float4*)(wrow + k4*4);
        #pragma unroll
        for (int i = 0; i < 4; ++i) {
            float4 av = *(const float4*)&sa[(rl*4 + i)*256 + k4*4];
            FMA4(acc[i], wv, av);
        }
    }
    float bb = b_fc[d];
    #pragma unroll
    for (int i = 0; i < 4; ++i)
        out[(r0 + rl*4 + i)*ND + d] = acc[i] + bb;
}

// ---------------- launch ----------------
extern "C" void kernel_launch(void* const* d_in, const int* in_sizes, int n_in,
                              void* d_out, int out_size)
{
    const float* x        = (const float*)d_in[0];
    const float* xmean    = (const float*)d_in[1];
    const int*   clus     = (const int*)  d_in[2];
    const float* W_i      = (const float*)d_in[3];
    const float* b_i      = (const float*)d_in[4];
    const float* W_f      = (const float*)d_in[5];
    const float* b_f      = (const float*)d_in[6];
    const float* W_o      = (const float*)d_in[7];
    const float* b_o      = (const float*)d_in[8];
    const float* W_c      = (const float*)d_in[9];
    const float* b_c      = (const float*)d_in[10];
    const float* W_fc     = (const float*)d_in[11];
    const float* b_fc     = (const float*)d_in[12];
    const float* gz_w     = (const float*)d_in[13];
    const float* gz_b     = (const float*)d_in[14];
    const float* gzp_w    = (const float*)d_in[15];
    const float* gzp_b    = (const float*)d_in[16];
    const float* memory   = (const float*)d_in[17];
    const float* local_w  = (const float*)d_in[18];
    const float* global_w = (const float*)d_in[19];
    float* out = (float*)d_out;

    cudaFuncSetAttribute(rnn_kernel, cudaFuncAttributeMaxDynamicSharedMemorySize, SMEM_BYTES);

    prep1<<<512, 256>>>(x, xmean, clus, gz_w, gz_b, gzp_w, gzp_b, memory, local_w);
    prep2<<<32, 512>>>(W_fc, b_fc, local_w);
    prep3<<<64, 512>>>(W_i, W_f, W_o, W_c, b_i, b_f, b_o, b_c, W_fc, b_fc);
    prep4<<<1536, 256>>>();
    rnn_kernel<<<GRID, NTHR, SMEM_BYTES>>>(global_w);
    out_gemm<<<3072, 256>>>(W_fc, b_fc, out);
}

// round 8
// speedup vs baseline: 4.3802x; 1.0262x over previous
#include <cuda_runtime.h>

#define NB 128
#define NT 96
#define ND 256
#define NH 256
#define NCM 512
#define KA 512
#define KC 1280
#define GRID 128
#define NTHR 512
#define NGRP 8            // 8 independent groups x 16 CTAs x 16 batches

typedef unsigned long long u64;

// smem layout (floats)
// C acts: [k=0..1279][pad 20] (batch 0..15 within group) ; partials reuse this region
#define C_PAD   20
#define A_ACT   (KC * C_PAD)             // 25600
#define A_PAD   12
#define A_PART  (A_ACT + KA * A_PAD)     // 31744 (512 slots * 5-pad = 2560)
#define A_SCORE (A_PART + 2560)          // 34304 (+512)
#define SMEM_FLOATS (A_SCORE + 512)      // 34816
#define SMEM_BYTES  (SMEM_FLOATS * 4)    // 139264 B

// ---------------- static device scratch ----------------
__device__ float g_Zb [NB*NT*ND];     // [b][t][d]
__device__ float g_ZPb[NB*NT*ND];
__device__ float g_LPb[NB*NT*ND];
__device__ float g_Zt [NT*ND*NB];     // [t][d][b]
__device__ float g_ZPt[NT*ND*NB];
__device__ float g_LPt[NT*ND*NB];
__device__ float g_hall[(NT+1)*NB*NH];  // [t][b][h] (for out_gemm)
__device__ float g_hT  [(NT+1)*NH*NB];  // [t][h][b] (for staging)
__device__ float g_c   [NB*NH];
__device__ float g_swT [NCM*NB];        // [cm][b]
__device__ float g_mm  [NCM*ND];
__device__ float g_memT[ND*NCM];
__device__ float g_W4r [4*NH*KC];     // row-major folded gate weights
__device__ float g_W4q [4*NH*KC];     // blocked [g][k4][hh][4]
__device__ float g_b4  [4*NH];
__device__ float g_Wscr[NCM*KA];      // row-major folded score weights
__device__ float g_Wscq[NCM*KA];      // blocked [k4][cm][4]
__device__ float g_csc [NCM];
__device__ unsigned int g_garrive [NGRP*64];
__device__ unsigned int g_grelease[NGRP*64];

#define FMA4(ACC, WV, AV) ACC = fmaf((WV).x,(AV).x, fmaf((WV).y,(AV).y, fmaf((WV).z,(AV).z, fmaf((WV).w,(AV).w,(ACC)))))

// ---- packed fp32x2 helpers (bit-exact fp32, 2 MACs per FMA-pipe issue) ----
__device__ __forceinline__ void ffma2(u64& acc, u64 a, u64 b) {
    asm("fma.rn.f32x2 %0, %1, %2, %0;" : "+l"(acc) : "l"(a), "l"(b));
}
__device__ __forceinline__ u64 dup2(float v) {
    u64 r; asm("mov.b64 %0, {%1, %1};" : "=l"(r) : "f"(v)); return r;
}
__device__ __forceinline__ void unpack2(u64 v, float& lo, float& hi) {
    asm("mov.b64 {%0, %1}, %2;" : "=f"(lo), "=f"(hi) : "l"(v));
}

// ---------------- prep1: z/zp/LP (b-major), masked memory, memT, state + barrier init ----------------
__global__ void prep1(const float* __restrict__ x, const float* __restrict__ xmean,
                      const int* __restrict__ cl32,
                      const float* __restrict__ gz_w,  const float* __restrict__ gz_b,
                      const float* __restrict__ gzp_w, const float* __restrict__ gzp_b,
                      const float* __restrict__ memory, const float* __restrict__ local_w)
{
    int tid  = blockIdx.x * blockDim.x + threadIdx.x;
    int nthr = gridDim.x * blockDim.x;
    bool is64 = (cl32[1] == 0);   // cluster vals are 1..8 -> int64 high word of elem0 is 0

    for (int i = tid; i < NB*NT*ND; i += nthr) {
        int d = i & (ND - 1);
        int t = (i / ND) % NT;
        int b = i / (ND * NT);
        long long o = (((long long)b * 6) * NT + t) * ND + d;
        float xt  = x[o];
        float xl  = x[o + 1ll*NT*ND];
        float mk  = x[o + 2ll*NT*ND];
        float dt  = x[o + 3ll*NT*ND];
        float xlb = x[o + 4ll*NT*ND];
        float dtb = x[o + 5ll*NT*ND];
        float mean = xmean[t*ND + d];
        float dz  = expf(-fmaxf(dt  * gz_w[d]  + gz_b[d],  0.f));
        float dzp = expf(-fmaxf(dtb * gzp_w[d] + gzp_b[d], 0.f));
        float z  = mk*xt + (1.f - mk)*(dz *xl  + (1.f - dz )*mean);
        float zp = mk*xt + (1.f - mk)*(dzp*xlb + (1.f - dzp)*mean);
        g_Zb[i]  = z;
        g_ZPb[i] = zp;
        g_LPb[i] = local_w[d]*z + local_w[ND + d]*zp;
    }
    for (int i = tid; i < NCM*ND; i += nthr) {
        int d  = i & (ND - 1);
        int c  = i / (64 * ND);
        int cv = is64 ? cl32[2*d] : cl32[d];
        g_mm[i] = (cv == c + 1) ? memory[i] : 0.f;
    }
    for (int i = tid; i < ND*NCM; i += nthr) {
        int d = i / NCM, cm = i % NCM;
        g_memT[i] = memory[cm*ND + d];
    }
    for (int i = tid; i < NB*NH; i += nthr) {
        g_hall[i] = 0.f; g_hT[i] = 0.f; g_c[i] = 0.f;
    }
    if (tid < NGRP*64) { g_garrive[tid] = 0u; g_grelease[tid] = 0u; }
}

// ---------------- transpose [128][24576] -> [24576][128] for Z, ZP, LP ----------------
__global__ void transpose_k()
{
    __shared__ float tile[32][33];
    const float* src = (blockIdx.z == 0) ? g_Zb : (blockIdx.z == 1) ? g_ZPb : g_LPb;
    float*       dst = (blockIdx.z == 0) ? g_Zt : (blockIdx.z == 1) ? g_ZPt : g_LPt;
    const int COLS = NT*ND;   // 24576
    int col0 = blockIdx.x * 32, row0 = blockIdx.y * 32;
    int tx = threadIdx.x, ty = threadIdx.y;   // 32 x 8
    #pragma unroll
    for (int j = 0; j < 32; j += 8)
        tile[ty + j][tx] = src[(row0 + ty + j) * COLS + col0 + tx];
    __syncthreads();
    #pragma unroll
    for (int j = 0; j < 32; j += 8)
        dst[(col0 + ty + j) * NB + row0 + tx] = tile[tx][ty + j];
}

// ---------------- prep2: folded score weights (row-major) + csc ----------------
__global__ void prep2(const float* __restrict__ W_fc, const float* __restrict__ b_fc,
                      const float* __restrict__ local_w)
{
    __shared__ float A[16*256];
    int cmt = blockIdx.x;            // 0..31 (16 cm rows each)
    int tid = threadIdx.x;           // 512
    for (int idx = tid; idx < 16*256; idx += 512) {
        int ci = idx >> 8, d = idx & 255;
        float mmv = g_mm[(cmt*16 + ci)*ND + d];
        A[idx] = local_w[2*ND + d] * mmv;
        g_Wscr[(cmt*16 + ci)*KA + d] = mmv;
    }
    __syncthreads();
    int j = tid & 255, half = tid >> 8;
    float acc[8];
    #pragma unroll
    for (int i = 0; i < 8; ++i) acc[i] = 0.f;
    for (int d = 0; d < 256; ++d) {
        float wf = W_fc[d*ND + j];
        #pragma unroll
        for (int i = 0; i < 8; ++i) acc[i] = fmaf(A[(half*8+i)*256 + d], wf, acc[i]);
    }
    #pragma unroll
    for (int i = 0; i < 8; ++i)
        g_Wscr[(cmt*16 + half*8 + i)*KA + 256 + j] = acc[i];
    if (tid < 16) {
        float s = 0.f;
        for (int d = 0; d < 256; ++d) s += A[tid*256 + d] * b_fc[d];
        g_csc[cmt*16 + tid] = s;
    }
}

// ---------------- prep3: folded gate weights (row-major) + folded bias ----------------
// K layout: [0:512)=z,zp, [512:1024)=s' (gd fold), [1024:1280)=h (+ x_i fold)
__global__ void prep3(const float* __restrict__ W_i, const float* __restrict__ W_f,
                      const float* __restrict__ W_o, const float* __restrict__ W_c,
                      const float* __restrict__ b_i, const float* __restrict__ b_f,
                      const float* __restrict__ b_o, const float* __restrict__ b_c,
                      const float* __restrict__ W_fc, const float* __restrict__ b_fc)
{
    __shared__ float A1[16*256];   // gd segment  (orig cols 768:1024)
    __shared__ float A2[16*256];   // x_i segment (orig cols 512:768)
    int g = blockIdx.x >> 4, hht = blockIdx.x & 15;
    const float* Wg = (g == 0) ? W_i : (g == 1) ? W_f : (g == 2) ? W_o : W_c;
    const float* bg = (g == 0) ? b_i : (g == 1) ? b_f : (g == 2) ? b_o : b_c;
    int tid = threadIdx.x;   // 512

    for (int idx = tid; idx < 16*256; idx += 512) {
        int hi = idx >> 8, d = idx & 255;
        int row = hht*16 + hi;
        A1[idx] = Wg[row*KC + 768 + d];
        A2[idx] = Wg[row*KC + 512 + d];
    }
    for (int idx = tid; idx < 16*512; idx += 512) {     // z,zp segments verbatim
        int hi = idx >> 9, k = idx & 511;
        int row = hht*16 + hi;
        g_W4r[(g*NH + row)*KC + k] = Wg[row*KC + k];
    }
    __syncthreads();
    {   // h segment: W[hh,1024+j] + sum_d A2[hh,d]*W_fc[d,j]
        int j = tid & 255, half = tid >> 8;
        float acc[8];
        #pragma unroll
        for (int i = 0; i < 8; ++i) acc[i] = 0.f;
        for (int d = 0; d < 256; ++d) {
            float wf = W_fc[d*ND + j];
            #pragma unroll
            for (int i = 0; i < 8; ++i) acc[i] = fmaf(A2[(half*8+i)*256 + d], wf, acc[i]);
        }
        #pragma unroll
        for (int i = 0; i < 8; ++i) {
            int hhr = hht*16 + half*8 + i;
            g_W4r[(g*NH + hhr)*KC + 1024 + j] = Wg[hhr*KC + 1024 + j] + acc[i];
        }
    }
    {   // s' segment: Wg2[hh,cm] = sum_d A1[hh,d]*mem[cm,d]
        int cm = tid;
        float acc[16];
        #pragma unroll
        for (int i = 0; i < 16; ++i) acc[i] = 0.f;
        for (int d = 0; d < 256; ++d) {
            float mt = g_memT[d*NCM + cm];
            #pragma unroll
            for (int i = 0; i < 16; ++i) acc[i] = fmaf(A1[i*256 + d], mt, acc[i]);
        }
        #pragma unroll
        for (int i = 0; i < 16; ++i)
            g_W4r[(g*NH + hht*16 + i)*KC + 512 + cm] = acc[i];
    }
    if (tid < 16) {   // bias fold
        float s = 0.f;
        for (int d = 0; d < 256; ++d) s += A2[tid*256 + d] * b_fc[d];
        g_b4[g*NH + hht*16 + tid] = bg[hht*16 + tid] + s;
    }
}

// ---------------- prep4: blocked (coalesced-LDG) layouts ----------------
__global__ void prep4()
{
    int idx = blockIdx.x * blockDim.x + threadIdx.x;
    if (idx < 4*320*256) {               // g_W4q[((g*320+k4)*256+hh)*4]
        int hh = idx & 255;
        int gk = idx >> 8;
        int g = gk / 320, k4 = gk % 320;
        *(float4*)&g_W4q[idx*4] = *(const float4*)&g_W4r[(g*NH + hh)*KC + k4*4];
    }
    int j = idx - 4*320*256;
    if (j >= 0 && j < 128*512) {         // g_Wscq[(k4*512+cm)*4]
        int cm = j & 511, k4 = j >> 9;
        *(float4*)&g_Wscq[j*4] = *(const float4*)&g_Wscr[cm*KA + k4*4];
    }
}

// ---------------- per-group barrier (16 CTAs; monotonic; reset by prep1) ----------------
__device__ __forceinline__ void group_sync(int grp, unsigned int& gen)
{
    __syncthreads();
    if (threadIdx.x == 0) {
        __threadfence();
        unsigned int target = gen + 1u;
        unsigned int a = atomicAdd(&g_garrive[grp*64], 1u) + 1u;
        if (a == target * 16u) {
            atomicExch(&g_grelease[grp*64], target);
        } else {
            volatile unsigned int* rel = &g_grelease[grp*64];
            while (*rel < target) { }
        }
        __threadfence();
    }
    gen += 1u;
    __syncthreads();
}

// ---------------- persistent recurrence: 8 independent groups, f32x2 math ----------------
__global__ void __launch_bounds__(NTHR, 1)
rnn_kernel(const float* __restrict__ global_w)
{
    extern __shared__ float sm[];
    const int cta = blockIdx.x, tid = threadIdx.x;
    const int lane = tid & 31, wid = tid >> 5;
    const int grp = cta >> 4, local = cta & 15;
    // phase A: local = (bhalf:2 x 8 batches, ccl:8 clusters); thread = (a_ml:64, a_bh:2, a_ks:4)
    const int bhalf = local >> 3, ccl = local & 7;
    const int a_b0 = grp*16 + bhalf*8;
    const int a_ml = tid & 63, a_bh = (tid >> 6) & 1, a_ks = tid >> 7;
    // phase C: local = sub (16 hh slice); thread = (c_hl:16, c_bq:4, c_ks:8)
    const int sub = local;
    const int c_b0 = grp*16;
    const int c_hl = tid & 15, c_bq = (tid >> 4) & 3, c_ks = tid >> 6;
    const int hh = sub*16 + c_hl;
    unsigned int gen = 0;

    // pre-stage A acts for t=0: LP(0) rows [0:256), h(0) rows [256:512)
    for (int idx = tid; idx < 2*512; idx += NTHR) {
        int b4 = idx & 1, k = idx >> 1;
        float4 v;
        if (k < 256) v = *(const float4*)&g_LPt[(0*256 + k)*NB + a_b0 + b4*4];
        else         v = __ldcg((const float4*)&g_hT[(k-256)*NB + a_b0 + b4*4]);
        *(float4*)&sm[A_ACT + k*A_PAD + b4*4] = v;
    }
    __syncthreads();

    for (int t = 0; t < NT; ++t) {
        // ===== Phase A: scores + softmax -> s'(t) in g_swT =====
        {
            u64 acc2[2] = {0ull, 0ull};
            {
                const float4* wp = (const float4*)g_Wscq + (a_ks*32)*NCM + (ccl*64 + a_ml);
                const float*  ak = sm + A_ACT + (a_ks*128)*A_PAD + a_bh*4;
                #pragma unroll 4
                for (int it = 0; it < 32; ++it) {
                    float4 wv = wp[it*NCM];
                    const float* ap = ak + it*4*A_PAD;
                    #define ASTEP(OFF, COMP) { \
                        u64 a0 = *(const u64*)(ap + (OFF)*A_PAD); \
                        u64 a1 = *(const u64*)(ap + (OFF)*A_PAD + 2); \
                        u64 wd_ = dup2(wv.COMP); \
                        ffma2(acc2[0], wd_, a0); ffma2(acc2[1], wd_, a1); }
                    ASTEP(0, x) ASTEP(1, y) ASTEP(2, z) ASTEP(3, w)
                    #undef ASTEP
                }
            }
            {
                float a0, a1, a2, a3;
                unpack2(acc2[0], a0, a1);
                unpack2(acc2[1], a2, a3);
                int base = A_PART + ((a_ks*64 + a_ml)*2 + a_bh)*5;
                sm[base + 0] = a0; sm[base + 1] = a1;
                sm[base + 2] = a2; sm[base + 3] = a3;
            }
            __syncthreads();
            {   // reduce over a_ks + csc bias; bl = batch index (bh=bl>>2, j=bl&3)
                int bl = tid >> 6, m = tid & 63;
                float s = g_csc[ccl*64 + m];
                #pragma unroll
                for (int ks = 0; ks < 4; ++ks)
                    s += sm[A_PART + ((ks*64 + m)*2 + (bl >> 2))*5 + (bl & 3)];
                sm[A_SCORE + bl*64 + m] = s;
            }
            __syncthreads();
            if (wid < 8) {   // softmax over 64 m for batch wid; scale by global_w[ccl]
                float v0 = sm[A_SCORE + wid*64 + lane];
                float v1 = sm[A_SCORE + wid*64 + 32 + lane];
                float mx = fmaxf(v0, v1);
                #pragma unroll
                for (int o = 16; o; o >>= 1) mx = fmaxf(mx, __shfl_xor_sync(0xffffffffu, mx, o));
                float e0 = expf(v0 - mx), e1 = expf(v1 - mx);
                float s = e0 + e1;
                #pragma unroll
                for (int o = 16; o; o >>= 1) s += __shfl_xor_sync(0xffffffffu, s, o);
                float sc = global_w[ccl] / s;
                int b = a_b0 + wid;
                __stcg(&g_swT[(ccl*64 + lane)*NB + b],      e0*sc);
                __stcg(&g_swT[(ccl*64 + 32 + lane)*NB + b], e1*sc);
            }
        }

        // stage C z/zp(t) (h-independent) BEFORE the barrier: rows [0:512)
        for (int idx = tid; idx < 4*512; idx += NTHR) {
            int b4 = idx & 3, k = idx >> 2;
            float4 v;
            if (k < 256) v = *(const float4*)&g_Zt [(t*256 + k)*NB + c_b0 + b4*4];
            else         v = *(const float4*)&g_ZPt[(t*256 + (k-256))*NB + c_b0 + b4*4];
            *(float4*)&sm[k*C_PAD + b4*4] = v;
        }
        group_sync(grp, gen);        // group's g_swT complete

        // stage C s'(t) rows [512:1024) + h(t) rows [1024:1280)
        for (int idx = tid; idx < 4*768; idx += NTHR) {
            int b4 = idx & 3, kr = idx >> 2;
            float4 v;
            if (kr < 512) v = __ldcg((const float4*)&g_swT[kr*NB + c_b0 + b4*4]);
            else          v = __ldcg((const float4*)&g_hT[(t*256 + (kr-512))*NB + c_b0 + b4*4]);
            *(float4*)&sm[(512 + kr)*C_PAD + b4*4] = v;
        }
        __syncthreads();

        // ===== Phase C: 4-gate GEMM over K=1280 [z,zp,s',h]; f32x2 packed =====
        {
            u64 acc2[8];
            #pragma unroll
            for (int i = 0; i < 8; ++i) acc2[i] = 0ull;
            {
                const int k40 = c_ks * 40;
                const float4* w0 = (const float4*)g_W4q + ((0*320 + k40)*NH + hh);
                const float4* w1 = (const float4*)g_W4q + ((1*320 + k40)*NH + hh);
                const float4* w2 = (const float4*)g_W4q + ((2*320 + k40)*NH + hh);
                const float4* w3 = (const float4*)g_W4q + ((3*320 + k40)*NH + hh);
                const float*  ak = sm + (c_ks*160)*C_PAD + c_bq*4;
                #pragma unroll 2
                for (int it = 0; it < 40; ++it) {
                    float4 wva = w0[it*NH];
                    float4 wvb = w1[it*NH];
                    float4 wvc = w2[it*NH];
                    float4 wvd = w3[it*NH];
                    const float* ap = ak + it*4*C_PAD;
                    #define CSTEP(OFF, COMP) { \
                        u64 a0 = *(const u64*)(ap + (OFF)*C_PAD); \
                        u64 a1 = *(const u64*)(ap + (OFF)*C_PAD + 2); \
                        u64 p_; \
                        p_ = dup2(wva.COMP); ffma2(acc2[0], p_, a0); ffma2(acc2[1], p_, a1); \
                        p_ = dup2(wvb.COMP); ffma2(acc2[2], p_, a0); ffma2(acc2[3], p_, a1); \
                        p_ = dup2(wvc.COMP); ffma2(acc2[4], p_, a0); ffma2(acc2[5], p_, a1); \
                        p_ = dup2(wvd.COMP); ffma2(acc2[6], p_, a0); ffma2(acc2[7], p_, a1); }
                    CSTEP(0, x) CSTEP(1, y) CSTEP(2, z) CSTEP(3, w)
                    #undef CSTEP
                }
            }
            __syncthreads();                         // act region reused for partials
            {
                float tmp[16];
                #pragma unroll
                for (int g = 0; g < 4; ++g) {
                    unpack2(acc2[g*2 + 0], tmp[g*4 + 0], tmp[g*4 + 1]);
                    unpack2(acc2[g*2 + 1], tmp[g*4 + 2], tmp[g*4 + 3]);
                }
                int base = (c_ks*64 + c_bq*16 + c_hl)*17;   // pad-17: conflict-free
                #pragma unroll
                for (int v = 0; v < 16; ++v) sm[base + v] = tmp[v];
            }
            __syncthreads();
            if (tid < 256) {   // (hl2:16, bi:16): reduce 8 ks, gates, state update
                int hl2 = tid & 15, bi = tid >> 4;
                int bq = bi >> 2, j = bi & 3;
                int b = c_b0 + bi, h2 = sub*16 + hl2;
                float gg[4];
                #pragma unroll
                for (int g = 0; g < 4; ++g) {
                    float s = g_b4[g*NH + h2];
                    #pragma unroll
                    for (int ks = 0; ks < 8; ++ks)
                        s += sm[(ks*64 + bq*16 + hl2)*17 + g*4 + j];
                    gg[g] = s;
                }
                float ig = 1.f / (1.f + expf(-gg[0]));
                float fg = 1.f / (1.f + expf(-gg[1]));
                float og = 1.f / (1.f + expf(-gg[2]));
                float cg = tanhf(gg[3]);
                float cn = fg * g_c[b*NH + h2] + ig * cg;
                g_c[b*NH + h2] = cn;
                float hn = og * tanhf(cn);
                g_hall[(((t+1)*NB + b) << 8) + h2] = hn;            // for out_gemm
                __stcg(&g_hT[((t+1)*256 + h2)*NB + b], hn);         // for staging
            }
        }

        // stage A LP(t+1) (h-independent) BEFORE the barrier: rows [0:256)
        if (t + 1 < NT) {
            for (int idx = tid; idx < 2*256; idx += NTHR) {
                int b4 = idx & 1, k = idx >> 1;
                *(float4*)&sm[A_ACT + k*A_PAD + b4*4] =
                    *(const float4*)&g_LPt[((t+1)*256 + k)*NB + a_b0 + b4*4];
            }
        }
        group_sync(grp, gen);        // group's h(t+1) complete

        if (t + 1 < NT) {            // stage A h(t+1): rows [256:512)
            for (int idx = tid; idx < 2*256; idx += NTHR) {
                int b4 = idx & 1, k = idx >> 1;
                *(float4*)&sm[A_ACT + (256 + k)*A_PAD + b4*4] =
                    __ldcg((const float4*)&g_hT[((t+1)*256 + k)*NB + a_b0 + b4*4]);
            }
            __syncthreads();
        }
    }
}

// ---------------- final: out[b,t,:] = h_{t+1} @ W_fc^T + b_fc ----------------
__global__ void out_gemm(const float* __restrict__ W_fc, const float* __restrict__ b_fc,
                         float* __restrict__ out)
{
    __shared__ float sa[16*256];     // 16 KB
    int rt = blockIdx.x >> 2, dt = blockIdx.x & 3;
    int tid = threadIdx.x;           // 256
    int r0 = rt * 16;
    for (int idx = tid; idx < 16*64; idx += 256) {
        int row = idx >> 6, k4 = idx & 63;
        int r = r0 + row, b = r / NT, t = r % NT;
        *(float4*)&sa[row*256 + k4*4] =
            *(const float4*)&g_hall[(((t+1)*NB + b) << 8) + k4*4];
    }
    __syncthreads();
    int dl = tid & 63, rl = tid >> 6;
    int d = dt*64 + dl;
    float acc[4];
    #pragma unroll
    for (int i = 0; i < 4; ++i) acc[i] = 0.f;
    const float* wrow = W_fc + d*NH;
    #pragma unroll 4
    for (int k4 = 0; k4 < 64; ++k4) {
        float4 wv = *(const float4*)(wrow + k4*4);
        #pragma unroll
        for (int i = 0; i < 4; ++i) {
            float4 av = *(const float4*)&sa[(rl*4 + i)*256 + k4*4];
            FMA4(acc[i], wv, av);
        }
    }
    float bb = b_fc[d];
    #pragma unroll
    for (int i = 0; i < 4; ++i)
        out[(r0 + rl*4 + i)*ND + d] = acc[i] + bb;
}

// ---------------- launch ----------------
extern "C" void kernel_launch(void* const* d_in, const int* in_sizes, int n_in,
                              void* d_out, int out_size)
{
    const float* x        = (const float*)d_in[0];
    const float* xmean    = (const float*)d_in[1];
    const int*   clus     = (const int*)  d_in[2];
    const float* W_i      = (const float*)d_in[3];
    const float* b_i      = (const float*)d_in[4];
    const float* W_f      = (const float*)d_in[5];
    const float* b_f      = (const float*)d_in[6];
    const float* W_o      = (const float*)d_in[7];
    const float* b_o      = (const float*)d_in[8];
    const float* W_c      = (const float*)d_in[9];
    const float* b_c      = (const float*)d_in[10];
    const float* W_fc     = (const float*)d_in[11];
    const float* b_fc     = (const float*)d_in[12];
    const float* gz_w     = (const float*)d_in[13];
    const float* gz_b     = (const float*)d_in[14];
    const float* gzp_w    = (const float*)d_in[15];
    const float* gzp_b    = (const float*)d_in[16];
    const float* memory   = (const float*)d_in[17];
    const float* local_w  = (const float*)d_in[18];
    const float* global_w = (const float*)d_in[19];
    float* out = (float*)d_out;

    cudaFuncSetAttribute(rnn_kernel, cudaFuncAttributeMaxDynamicSharedMemorySize, SMEM_BYTES);

    prep1<<<512, 256>>>(x, xmean, clus, gz_w, gz_b, gzp_w, gzp_b, memory, local_w);
    {
        dim3 tg(NT*ND/32, NB/32, 3);      // 768 x 4 x 3
        transpose_k<<<tg, dim3(32, 8)>>>();
    }
    prep2<<<32, 512>>>(W_fc, b_fc, local_w);
    prep3<<<64, 512>>>(W_i, W_f, W_o, W_c, b_i, b_f, b_o, b_c, W_fc, b_fc);
    prep4<<<1536, 256>>>();
    rnn_kernel<<<GRID, NTHR, SMEM_BYTES>>>(global_w);
    out_gemm<<<3072, 256>>>(W_fc, b_fc, out);
}

// round 9
// speedup vs baseline: 4.5158x; 1.0310x over previous
#include <cuda_runtime.h>

#define NB 128
#define NT 96
#define ND 256
#define NH 256
#define NCM 512
#define KA 512
#define KC 1280
#define GRID 128
#define NTHR 512
#define NGRP 8

typedef unsigned long long u64;

// smem layout (floats)
#define C_PAD   20
#define A_ACT   (KC * C_PAD)             // 25600
#define A_PAD   12
#define A_PART  (A_ACT + KA * A_PAD)     // 31744
#define A_SCORE (A_PART + 2560)          // 34304
#define SMEM_FLOATS (A_SCORE + 512)      // 34816
#define SMEM_BYTES  (SMEM_FLOATS * 4)    // 139264 B

// ---------------- static device scratch ----------------
__device__ float g_Zb [NB*NT*ND];
__device__ float g_ZPb[NB*NT*ND];
__device__ float g_LPb[NB*NT*ND];
__device__ float g_Zt [NT*ND*NB];
__device__ float g_ZPt[NT*ND*NB];
__device__ float g_LPt[NT*ND*NB];
__device__ float g_hall[(NT+1)*NB*NH];   // [t][b][h]
__device__ float g_hT  [(NT+1)*NH*NB];   // [t][h][b]
__device__ float g_swT [NCM*NB];         // [cm][b]
__device__ float g_mm  [NCM*ND];
__device__ float g_memT[ND*NCM];
__device__ float g_W4r [4*NH*KC];        // row-major folded gate weights (dc0 part)
__device__ float g_W4p [4*NH*768];       // dc1 partial for cols [512:1280)
__device__ float g_W4q [4*NH*KC + 4096]; // blocked [g][k4][hh][4], padded for prefetch
__device__ float g_b4a [4*NH];
__device__ float g_b4b [4*NH];
__device__ float g_b4  [4*NH];
__device__ float g_Wscr[NCM*KA];
__device__ float g_Wscq[NCM*KA + 6144];  // blocked [k4][cm][4], padded for prefetch
__device__ float g_csc [NCM];
__device__ unsigned int g_garrive [NGRP*64];
__device__ unsigned int g_grelease[NGRP*64];

#define FMA4(ACC, WV, AV) ACC = fmaf((WV).x,(AV).x, fmaf((WV).y,(AV).y, fmaf((WV).z,(AV).z, fmaf((WV).w,(AV).w,(ACC)))))

// ---- packed fp32x2 helpers ----
__device__ __forceinline__ void ffma2(u64& acc, u64 a, u64 b) {
    asm("fma.rn.f32x2 %0, %1, %2, %0;" : "+l"(acc) : "l"(a), "l"(b));
}
__device__ __forceinline__ u64 dup2(float v) {
    u64 r; asm("mov.b64 %0, {%1, %1};" : "=l"(r) : "f"(v)); return r;
}
__device__ __forceinline__ void unpack2(u64 v, float& lo, float& hi) {
    asm("mov.b64 {%0, %1}, %2;" : "=f"(lo), "=f"(hi) : "l"(v));
}

// ---- acquire/release sync primitives ----
__device__ __forceinline__ unsigned atom_add_acqrel(unsigned* p, unsigned v) {
    unsigned r;
    asm volatile("atom.acq_rel.gpu.add.u32 %0, [%1], %2;" : "=r"(r) : "l"(p), "r"(v) : "memory");
    return r;
}
__device__ __forceinline__ unsigned ld_acquire(unsigned* p) {
    unsigned r;
    asm volatile("ld.acquire.gpu.u32 %0, [%1];" : "=r"(r) : "l"(p) : "memory");
    return r;
}
__device__ __forceinline__ void st_release(unsigned* p, unsigned v) {
    asm volatile("st.release.gpu.u32 [%0], %1;" :: "l"(p), "r"(v) : "memory");
}

// ---------------- prep1 ----------------
__global__ void prep1(const float* __restrict__ x, const float* __restrict__ xmean,
                      const int* __restrict__ cl32,
                      const float* __restrict__ gz_w,  const float* __restrict__ gz_b,
                      const float* __restrict__ gzp_w, const float* __restrict__ gzp_b,
                      const float* __restrict__ memory, const float* __restrict__ local_w)
{
    int tid  = blockIdx.x * blockDim.x + threadIdx.x;
    int nthr = gridDim.x * blockDim.x;
    bool is64 = (cl32[1] == 0);   // cluster vals 1..8 -> int64 high word of elem0 is 0

    for (int i = tid; i < NB*NT*ND; i += nthr) {
        int d = i & (ND - 1);
        int t = (i / ND) % NT;
        int b = i / (ND * NT);
        long long o = (((long long)b * 6) * NT + t) * ND + d;
        float xt  = x[o];
        float xl  = x[o + 1ll*NT*ND];
        float mk  = x[o + 2ll*NT*ND];
        float dt  = x[o + 3ll*NT*ND];
        float xlb = x[o + 4ll*NT*ND];
        float dtb = x[o + 5ll*NT*ND];
        float mean = xmean[t*ND + d];
        float dz  = expf(-fmaxf(dt  * gz_w[d]  + gz_b[d],  0.f));
        float dzp = expf(-fmaxf(dtb * gzp_w[d] + gzp_b[d], 0.f));
        float z  = mk*xt + (1.f - mk)*(dz *xl  + (1.f - dz )*mean);
        float zp = mk*xt + (1.f - mk)*(dzp*xlb + (1.f - dzp)*mean);
        g_Zb[i]  = z;
        g_ZPb[i] = zp;
        g_LPb[i] = local_w[d]*z + local_w[ND + d]*zp;
    }
    for (int i = tid; i < NCM*ND; i += nthr) {
        int d  = i & (ND - 1);
        int c  = i / (64 * ND);
        int cv = is64 ? cl32[2*d] : cl32[d];
        g_mm[i] = (cv == c + 1) ? memory[i] : 0.f;
    }
    for (int i = tid; i < ND*NCM; i += nthr) {
        int d = i / NCM, cm = i % NCM;
        g_memT[i] = memory[cm*ND + d];
    }
    for (int i = tid; i < NB*NH; i += nthr) { g_hall[i] = 0.f; g_hT[i] = 0.f; }
    if (tid < NGRP*64) { g_garrive[tid] = 0u; g_grelease[tid] = 0u; }
}

// ---------------- transpose [128][24576] -> [24576][128] ----------------
__global__ void transpose_k()
{
    __shared__ float tile[32][33];
    const float* src = (blockIdx.z == 0) ? g_Zb : (blockIdx.z == 1) ? g_ZPb : g_LPb;
    float*       dst = (blockIdx.z == 0) ? g_Zt : (blockIdx.z == 1) ? g_ZPt : g_LPt;
    const int COLS = NT*ND;
    int col0 = blockIdx.x * 32, row0 = blockIdx.y * 32;
    int tx = threadIdx.x, ty = threadIdx.y;
    #pragma unroll
    for (int j = 0; j < 32; j += 8)
        tile[ty + j][tx] = src[(row0 + ty + j) * COLS + col0 + tx];
    __syncthreads();
    #pragma unroll
    for (int j = 0; j < 32; j += 8)
        dst[(col0 + ty + j) * NB + row0 + tx] = tile[tx][ty + j];
}

// ---------------- prep2: folded score weights + csc ----------------
__global__ void prep2(const float* __restrict__ W_fc, const float* __restrict__ b_fc,
                      const float* __restrict__ local_w)
{
    __shared__ float A[16*256];
    int cmt = blockIdx.x;            // 0..31
    int tid = threadIdx.x;           // 512
    for (int idx = tid; idx < 16*256; idx += 512) {
        int ci = idx >> 8, d = idx & 255;
        float mmv = g_mm[(cmt*16 + ci)*ND + d];
        A[idx] = local_w[2*ND + d] * mmv;
        g_Wscr[(cmt*16 + ci)*KA + d] = mmv;
    }
    __syncthreads();
    int j = tid & 255, half = tid >> 8;
    float acc[8];
    #pragma unroll
    for (int i = 0; i < 8; ++i) acc[i] = 0.f;
    for (int d = 0; d < 256; ++d) {
        float wf = W_fc[d*ND + j];
        #pragma unroll
        for (int i = 0; i < 8; ++i) acc[i] = fmaf(A[(half*8+i)*256 + d], wf, acc[i]);
    }
    #pragma unroll
    for (int i = 0; i < 8; ++i)
        g_Wscr[(cmt*16 + half*8 + i)*KA + 256 + j] = acc[i];
    if (tid < 16) {
        float s = 0.f;
        for (int d = 0; d < 256; ++d) s += A[tid*256 + d] * b_fc[d];
        g_csc[cmt*16 + tid] = s;
    }
}

// ---------------- prep3: folded gate weights, 2-way d-split, disjoint partials ----------------
__global__ void prep3(const float* __restrict__ W_i, const float* __restrict__ W_f,
                      const float* __restrict__ W_o, const float* __restrict__ W_c,
                      const float* __restrict__ b_i, const float* __restrict__ b_f,
                      const float* __restrict__ b_o, const float* __restrict__ b_c,
                      const float* __restrict__ W_fc, const float* __restrict__ b_fc)
{
    __shared__ float A1[16*128];
    __shared__ float A2[16*128];
    int bx = blockIdx.x;                 // 128 blocks
    int g = bx >> 5, hht = (bx >> 1) & 15, dc = bx & 1;
    int d0 = dc * 128;
    const float* Wg = (g == 0) ? W_i : (g == 1) ? W_f : (g == 2) ? W_o : W_c;
    const float* bg = (g == 0) ? b_i : (g == 1) ? b_f : (g == 2) ? b_o : b_c;
    int tid = threadIdx.x;   // 512

    for (int idx = tid; idx < 16*128; idx += 512) {
        int hi = idx >> 7, d = idx & 127;
        int row = hht*16 + hi;
        A1[idx] = Wg[row*KC + 768 + d0 + d];
        A2[idx] = Wg[row*KC + 512 + d0 + d];
    }
    if (dc == 0) {
        for (int idx = tid; idx < 16*512; idx += 512) {   // z,zp verbatim
            int hi = idx >> 9, k = idx & 511;
            int row = hht*16 + hi;
            g_W4r[(g*NH + row)*KC + k] = Wg[row*KC + k];
        }
    }
    __syncthreads();
    {   // h segment partial over this d half
        int j = tid & 255, half = tid >> 8;
        float acc[8];
        #pragma unroll
        for (int i = 0; i < 8; ++i) acc[i] = 0.f;
        for (int d = 0; d < 128; ++d) {
            float wf = W_fc[(d0 + d)*ND + j];
            #pragma unroll
            for (int i = 0; i < 8; ++i) acc[i] = fmaf(A2[(half*8+i)*128 + d], wf, acc[i]);
        }
        #pragma unroll
        for (int i = 0; i < 8; ++i) {
            int hhr = hht*16 + half*8 + i;
            if (dc == 0) g_W4r[(g*NH + hhr)*KC + 1024 + j] = Wg[hhr*KC + 1024 + j] + acc[i];
            else         g_W4p[(g*NH + hhr)*768 + 512 + j] = acc[i];
        }
    }
    {   // s' segment partial
        int cm = tid;
        float acc[16];
        #pragma unroll
        for (int i = 0; i < 16; ++i) acc[i] = 0.f;
        for (int d = 0; d < 128; ++d) {
            float mt = g_memT[(d0 + d)*NCM + cm];
            #pragma unroll
            for (int i = 0; i < 16; ++i) acc[i] = fmaf(A1[i*128 + d], mt, acc[i]);
        }
        #pragma unroll
        for (int i = 0; i < 16; ++i) {
            if (dc == 0) g_W4r[(g*NH + hht*16 + i)*KC + 512 + cm] = acc[i];
            else         g_W4p[(g*NH + hht*16 + i)*768 + cm] = acc[i];
        }
    }
    if (tid < 16) {   // bias partial
        float s = 0.f;
        for (int d = 0; d < 128; ++d) s += A2[tid*128 + d] * b_fc[d0 + d];
        if (dc == 0) g_b4a[g*NH + hht*16 + tid] = bg[hht*16 + tid] + s;
        else         g_b4b[g*NH + hht*16 + tid] = s;
    }
}

// ---------------- prep4: combine partials, build blocked layouts, combine bias ----------------
__global__ void prep4()
{
    int idx = blockIdx.x * blockDim.x + threadIdx.x;
    if (idx < 4*320*256) {
        int hh = idx & 255;
        int gk = idx >> 8;
        int g = gk / 320, k4 = gk % 320;
        float4 v = *(const float4*)&g_W4r[(g*NH + hh)*KC + k4*4];
        if (k4 >= 128) {
            float4 p = *(const float4*)&g_W4p[(g*NH + hh)*768 + (k4 - 128)*4];
            v.x += p.x; v.y += p.y; v.z += p.z; v.w += p.w;
        }
        *(float4*)&g_W4q[idx*4] = v;
        return;
    }
    int j = idx - 4*320*256;
    if (j < 128*512) {
        int cm = j & 511, k4 = j >> 9;
        *(float4*)&g_Wscq[j*4] = *(const float4*)&g_Wscr[cm*KA + k4*4];
        return;
    }
    int m = j - 128*512;
    if (m < 4*NH) g_b4[m] = g_b4a[m] + g_b4b[m];
}

// ---------------- per-group barrier (acq/rel; reset by prep1) ----------------
__device__ __forceinline__ void group_sync(int grp, unsigned int& gen)
{
    __syncthreads();
    if (threadIdx.x == 0) {
        unsigned int target = gen + 1u;
        unsigned int a = atom_add_acqrel(&g_garrive[grp*64], 1u) + 1u;
        if (a == target * 16u) {
            st_release(&g_grelease[grp*64], target);
        } else {
            while (ld_acquire(&g_grelease[grp*64]) < target) { }
        }
    }
    gen += 1u;
    __syncthreads();
}

// ---------------- persistent recurrence ----------------
__global__ void __launch_bounds__(NTHR, 1)
rnn_kernel(const float* __restrict__ global_w)
{
    extern __shared__ float sm[];
    const int cta = blockIdx.x, tid = threadIdx.x;
    const int lane = tid & 31, wid = tid >> 5;
    const int grp = cta >> 4, local = cta & 15;
    const int bhalf = local >> 3, ccl = local & 7;
    const int a_b0 = grp*16 + bhalf*8;
    const int a_ml = tid & 63, a_bh = (tid >> 6) & 1, a_ks = tid >> 7;
    const int sub = local;
    const int c_b0 = grp*16;
    const int c_hl = tid & 15, c_ks = tid >> 6;
    const int hh = sub*16 + c_hl;
    unsigned int gen = 0;

    // ---- thread-invariant register hoists ----
    float gwreg = global_w[ccl];                    // softmax scale
    float cscreg = g_csc[ccl*64 + (tid & 63)];      // reduce-stage bias
    float creg = 0.f;                               // LSTM cell state (tid<256 tail owns (b,h2))
    float bias0 = 0.f, bias1 = 0.f, bias2 = 0.f, bias3 = 0.f;
    if (tid < 256) {
        int h2 = sub*16 + (tid & 15);
        bias0 = g_b4[0*NH + h2];
        bias1 = g_b4[1*NH + h2];
        bias2 = g_b4[2*NH + h2];
        bias3 = g_b4[3*NH + h2];
    }

    // pre-stage A acts for t=0
    for (int idx = tid; idx < 2*512; idx += NTHR) {
        int b4i = idx & 1, k = idx >> 1;
        float4 v;
        if (k < 256) v = *(const float4*)&g_LPt[k*NB + a_b0 + b4i*4];
        else         v = __ldcg((const float4*)&g_hT[(k-256)*NB + a_b0 + b4i*4]);
        *(float4*)&sm[A_ACT + k*A_PAD + b4i*4] = v;
    }
    __syncthreads();

    for (int t = 0; t < NT; ++t) {
        // ===== Phase A: scores + softmax -> s'(t) =====
        {
            u64 acc2[2] = {0ull, 0ull};
            {
                const float4* wp = (const float4*)g_Wscq + (a_ks*32)*NCM + (ccl*64 + a_ml);
                const float*  ak = sm + A_ACT + (a_ks*128)*A_PAD + a_bh*4;
                #define ASTEP(APP, OFF, WV, COMP) { \
                    u64 a0_ = *(const u64*)((APP) + (OFF)*A_PAD); \
                    u64 a1_ = *(const u64*)((APP) + (OFF)*A_PAD + 2); \
                    u64 wd_ = dup2((WV).COMP); \
                    ffma2(acc2[0], wd_, a0_); ffma2(acc2[1], wd_, a1_); }
                #define ABLOCK(IT, WV) { \
                    const float* app_ = ak + (IT)*4*A_PAD; \
                    ASTEP(app_,0,WV,x) ASTEP(app_,1,WV,y) ASTEP(app_,2,WV,z) ASTEP(app_,3,WV,w) }
                float4 V0 = wp[0], V1 = wp[NCM];
                #pragma unroll 1
                for (int it = 0; it < 32; it += 2) {
                    float4 N0 = wp[(it+2)*NCM];     // prefetch depth 2 (padded array)
                    ABLOCK(it, V0)
                    float4 N1 = wp[(it+3)*NCM];
                    ABLOCK(it+1, V1)
                    V0 = N0; V1 = N1;
                }
                #undef ABLOCK
                #undef ASTEP
            }
            {
                float a0, a1, a2, a3;
                unpack2(acc2[0], a0, a1);
                unpack2(acc2[1], a2, a3);
                int base = A_PART + ((a_ks*64 + a_ml)*2 + a_bh)*5;
                sm[base + 0] = a0; sm[base + 1] = a1;
                sm[base + 2] = a2; sm[base + 3] = a3;
            }
            __syncthreads();
            {   // reduce over a_ks + csc bias
                int bl = tid >> 6, m = tid & 63;
                float s = cscreg;
                #pragma unroll
                for (int ks = 0; ks < 4; ++ks)
                    s += sm[A_PART + ((ks*64 + m)*2 + (bl >> 2))*5 + (bl & 3)];
                sm[A_SCORE + bl*64 + m] = s;
            }
            __syncthreads();
            if (wid < 8) {   // softmax for batch wid, scale by global_w[ccl]
                float v0 = sm[A_SCORE + wid*64 + lane];
                float v1 = sm[A_SCORE + wid*64 + 32 + lane];
                float mx = fmaxf(v0, v1);
                #pragma unroll
                for (int o = 16; o; o >>= 1) mx = fmaxf(mx, __shfl_xor_sync(0xffffffffu, mx, o));
                float e0 = expf(v0 - mx), e1 = expf(v1 - mx);
                float s = e0 + e1;
                #pragma unroll
                for (int o = 16; o; o >>= 1) s += __shfl_xor_sync(0xffffffffu, s, o);
                float sc = gwreg / s;
                int b = a_b0 + wid;
                __stcg(&g_swT[(ccl*64 + lane)*NB + b],      e0*sc);
                __stcg(&g_swT[(ccl*64 + 32 + lane)*NB + b], e1*sc);
            }
        }

        // stage C z/zp(t) BEFORE the barrier
        for (int idx = tid; idx < 4*512; idx += NTHR) {
            int b4i = idx & 3, k = idx >> 2;
            float4 v;
            if (k < 256) v = *(const float4*)&g_Zt [(t*256 + k)*NB + c_b0 + b4i*4];
            else         v = *(const float4*)&g_ZPt[(t*256 + (k-256))*NB + c_b0 + b4i*4];
            *(float4*)&sm[k*C_PAD + b4i*4] = v;
        }
        group_sync(grp, gen);

        // stage C s'(t) + h(t)
        for (int idx = tid; idx < 4*768; idx += NTHR) {
            int b4i = idx & 3, kr = idx >> 2;
            float4 v;
            if (kr < 512) v = __ldcg((const float4*)&g_swT[kr*NB + c_b0 + b4i*4]);
            else          v = __ldcg((const float4*)&g_hT[(t*256 + (kr-512))*NB + c_b0 + b4i*4]);
            *(float4*)&sm[(512 + kr)*C_PAD + b4i*4] = v;
        }
        __syncthreads();

        // ===== Phase C: 4-gate GEMM over K=1280; f32x2 + depth-2 weight prefetch =====
        {
            u64 acc2[8];
            #pragma unroll
            for (int i = 0; i < 8; ++i) acc2[i] = 0ull;
            {
                const int c_bq = (tid >> 4) & 3;
                const int k40 = c_ks * 40;
                const float4* w0 = (const float4*)g_W4q + ((0*320 + k40)*NH + hh);
                const float4* w1 = (const float4*)g_W4q + ((1*320 + k40)*NH + hh);
                const float4* w2 = (const float4*)g_W4q + ((2*320 + k40)*NH + hh);
                const float4* w3 = (const float4*)g_W4q + ((3*320 + k40)*NH + hh);
                const float*  ak = sm + (c_ks*160)*C_PAD + c_bq*4;
                #define CSTEP(APP, OFF, WA, WB, WC, WD, COMP) { \
                    u64 a0_ = *(const u64*)((APP) + (OFF)*C_PAD); \
                    u64 a1_ = *(const u64*)((APP) + (OFF)*C_PAD + 2); \
                    u64 p_; \
                    p_ = dup2((WA).COMP); ffma2(acc2[0], p_, a0_); ffma2(acc2[1], p_, a1_); \
                    p_ = dup2((WB).COMP); ffma2(acc2[2], p_, a0_); ffma2(acc2[3], p_, a1_); \
                    p_ = dup2((WC).COMP); ffma2(acc2[4], p_, a0_); ffma2(acc2[5], p_, a1_); \
                    p_ = dup2((WD).COMP); ffma2(acc2[6], p_, a0_); ffma2(acc2[7], p_, a1_); }
                #define CBLOCK(IT, WA, WB, WC, WD) { \
                    const float* app_ = ak + (IT)*4*C_PAD; \
                    CSTEP(app_,0,WA,WB,WC,WD,x) CSTEP(app_,1,WA,WB,WC,WD,y) \
                    CSTEP(app_,2,WA,WB,WC,WD,z) CSTEP(app_,3,WA,WB,WC,WD,w) }
                float4 Wa0 = w0[0],  Wb0 = w1[0],  Wc0 = w2[0],  Wd0 = w3[0];
                float4 Wa1 = w0[NH], Wb1 = w1[NH], Wc1 = w2[NH], Wd1 = w3[NH];
                #pragma unroll 1
                for (int it = 0; it < 40; it += 2) {
                    float4 Na = w0[(it+2)*NH], Nb = w1[(it+2)*NH],
                           Nc = w2[(it+2)*NH], Nd = w3[(it+2)*NH];   // prefetch (padded)
                    CBLOCK(it, Wa0, Wb0, Wc0, Wd0)
                    float4 Ma = w0[(it+3)*NH], Mb = w1[(it+3)*NH],
                           Mc = w2[(it+3)*NH], Md = w3[(it+3)*NH];
                    CBLOCK(it+1, Wa1, Wb1, Wc1, Wd1)
                    Wa0 = Na; Wb0 = Nb; Wc0 = Nc; Wd0 = Nd;
                    Wa1 = Ma; Wb1 = Mb; Wc1 = Mc; Wd1 = Md;
                }
                #undef CBLOCK
                #undef CSTEP
            }
            __syncthreads();
            {
                const int c_bq = (tid >> 4) & 3;
                float tmp[16];
                #pragma unroll
                for (int g = 0; g < 4; ++g) {
                    unpack2(acc2[g*2 + 0], tmp[g*4 + 0], tmp[g*4 + 1]);
                    unpack2(acc2[g*2 + 1], tmp[g*4 + 2], tmp[g*4 + 3]);
                }
                int base = (c_ks*64 + c_bq*16 + c_hl)*17;
                #pragma unroll
                for (int v = 0; v < 16; ++v) sm[base + v] = tmp[v];
            }
            __syncthreads();
            if (tid < 256) {   // (hl2:16, bi:16): reduce, gates, state in registers
                int hl2 = tid & 15, bi = tid >> 4;
                int bq = bi >> 2, j = bi & 3;
                int b = c_b0 + bi, h2 = sub*16 + hl2;
                float g0 = bias0, g1 = bias1, g2 = bias2, g3 = bias3;
                #pragma unroll
                for (int ks = 0; ks < 8; ++ks) {
                    const float* p = &sm[(ks*64 + bq*16 + hl2)*17 + j];
                    g0 += p[0]; g1 += p[4]; g2 += p[8]; g3 += p[12];
                }
                float ig = 1.f / (1.f + expf(-g0));
                float fg = 1.f / (1.f + expf(-g1));
                float og = 1.f / (1.f + expf(-g2));
                float cg = tanhf(g3);
                creg = fg * creg + ig * cg;
                float hn = og * tanhf(creg);
                g_hall[(((t+1)*NB + b) << 8) + h2] = hn;
                __stcg(&g_hT[((t+1)*256 + h2)*NB + b], hn);
            }
        }

        // stage A LP(t+1) BEFORE the barrier
        if (t + 1 < NT) {
            for (int idx = tid; idx < 2*256; idx += NTHR) {
                int b4i = idx & 1, k = idx >> 1;
                *(float4*)&sm[A_ACT + k*A_PAD + b4i*4] =
                    *(const float4*)&g_LPt[((t+1)*256 + k)*NB + a_b0 + b4i*4];
            }
        }
        group_sync(grp, gen);

        if (t + 1 < NT) {   // stage A h(t+1)
            for (int idx = tid; idx < 2*256; idx += NTHR) {
                int b4i = idx & 1, k = idx >> 1;
                *(float4*)&sm[A_ACT + (256 + k)*A_PAD + b4i*4] =
                    __ldcg((const float4*)&g_hT[((t+1)*256 + k)*NB + a_b0 + b4i*4]);
            }
            __syncthreads();
        }
    }
}

// ---------------- final: out[b,t,:] = h_{t+1} @ W_fc^T + b_fc ----------------
__global__ void out_gemm(const float* __restrict__ W_fc, const float* __restrict__ b_fc,
                         float* __restrict__ out)
{
    __shared__ float sa[16*256];
    int rt = blockIdx.x >> 2, dt = blockIdx.x & 3;
    int tid = threadIdx.x;           // 256
    int r0 = rt * 16;
    for (int idx = tid; idx < 16*64; idx += 256) {
        int row = idx >> 6, k4 = idx & 63;
        int r = r0 + row, b = r / NT, t = r % NT;
        *(float4*)&sa[row*256 + k4*4] =
            *(const float4*)&g_hall[(((t+1)*NB + b) << 8) + k4*4];
    }
    __syncthreads();
    int dl = tid & 63, rl = tid >> 6;
    int d = dt*64 + dl;
    float acc[4];
    #pragma unroll
    for (int i = 0; i < 4; ++i) acc[i] = 0.f;
    const float* wrow = W_fc + d*NH;
    #pragma unroll 4
    for (int k4 = 0; k4 < 64; ++k4) {
        float4 wv = *(const float4*)(wrow + k4*4);
        #pragma unroll
        for (int i = 0; i < 4; ++i) {
            float4 av = *(const float4*)&sa[(rl*4 + i)*256 + k4*4];
            FMA4(acc[i], wv, av);
        }
    }
    float bb = b_fc[d];
    #pragma unroll
    for (int i = 0; i < 4; ++i)
        out[(r0 + rl*4 + i)*ND + d] = acc[i] + bb;
}

// ---------------- launch ----------------
extern "C" void kernel_launch(void* const* d_in, const int* in_sizes, int n_in,
                              void* d_out, int out_size)
{
    const float* x        = (const float*)d_in[0];
    const float* xmean    = (const float*)d_in[1];
    const int*   clus     = (const int*)  d_in[2];
    const float* W_i      = (const float*)d_in[3];
    const float* b_i      = (const float*)d_in[4];
    const float* W_f      = (const float*)d_in[5];
    const float* b_f      = (const float*)d_in[6];
    const float* W_o      = (const float*)d_in[7];
    const float* b_o      = (const float*)d_in[8];
    const float* W_c      = (const float*)d_in[9];
    const float* b_c      = (const float*)d_in[10];
    const float* W_fc     = (const float*)d_in[11];
    const float* b_fc     = (const float*)d_in[12];
    const float* gz_w     = (const float*)d_in[13];
    const float* gz_b     = (const float*)d_in[14];
    const float* gzp_w    = (const float*)d_in[15];
    const float* gzp_b    = (const float*)d_in[16];
    const float* memory   = (const float*)d_in[17];
    const float* local_w  = (const float*)d_in[18];
    const float* global_w = (const float*)d_in[19];
    float* out = (float*)d_out;

    cudaFuncSetAttribute(rnn_kernel, cudaFuncAttributeMaxDynamicSharedMemorySize, SMEM_BYTES);

    prep1<<<512, 256>>>(x, xmean, clus, gz_w, gz_b, gzp_w, gzp_b, memory, local_w);
    {
        dim3 tg(NT*ND/32, NB/32, 3);
        transpose_k<<<tg, dim3(32, 8)>>>();
    }
    prep2<<<32, 512>>>(W_fc, b_fc, local_w);
    prep3<<<128, 512>>>(W_i, W_f, W_o, W_c, b_i, b_f, b_o, b_c, W_fc, b_fc);
    prep4<<<1540, 256>>>();
    rnn_kernel<<<GRID, NTHR, SMEM_BYTES>>>(global_w);
    out_gemm<<<3072, 256>>>(W_fc, b_fc, out);
}